// round 1
// baseline (speedup 1.0000x reference)
#include <cuda_runtime.h>
#include <cuda_bf16.h>
#include <math.h>

// ---------------- problem constants ----------------
#define BATCH 2
#define TOK   1024
#define ROWS  (BATCH*TOK)   // 2048
#define DMODEL 768
#define NHEAD 12
#define HD    64
#define NLAYER 4
#define VOCAB 50257
#define D3    (3*DMODEL)    // 2304
#define D4    (4*DMODEL)    // 3072

// ---------------- scratch (static device allocations) ----------------
__device__ float g_x   [ROWS*DMODEL];
__device__ float g_h   [ROWS*DMODEL];
__device__ float g_qkv [ROWS*D3];
__device__ float g_attn[ROWS*DMODEL];
__device__ float g_mlp [ROWS*D4];

// ---------------- embedding ----------------
__global__ void embed_kernel(const int* __restrict__ ids,
                             const float* __restrict__ wte,
                             const float* __restrict__ wpe,
                             float* __restrict__ x) {
    int idx = blockIdx.x * blockDim.x + threadIdx.x;
    if (idx >= ROWS*DMODEL) return;
    int row = idx / DMODEL;
    int d   = idx - row*DMODEL;
    int t   = row % TOK;
    x[idx] = wte[(long)ids[row]*DMODEL + d] + wpe[t*DMODEL + d];
}

// ---------------- layernorm (one block per row) ----------------
__global__ void layernorm_kernel(const float* __restrict__ x,
                                 const float* __restrict__ g,
                                 const float* __restrict__ b,
                                 float* __restrict__ out) {
    __shared__ float row[DMODEL];
    __shared__ float red[256];
    int r = blockIdx.x;
    int tid = threadIdx.x;
    const float* xr = x + (long)r*DMODEL;

    float s = 0.f;
    for (int i = tid; i < DMODEL; i += 256) { float v = xr[i]; row[i] = v; s += v; }
    red[tid] = s; __syncthreads();
    for (int off = 128; off > 0; off >>= 1) { if (tid < off) red[tid] += red[tid+off]; __syncthreads(); }
    float mean = red[0] * (1.f/DMODEL);
    __syncthreads();

    float vs = 0.f;
    for (int i = tid; i < DMODEL; i += 256) { float d = row[i] - mean; vs += d*d; }
    red[tid] = vs; __syncthreads();
    for (int off = 128; off > 0; off >>= 1) { if (tid < off) red[tid] += red[tid+off]; __syncthreads(); }
    float inv = rsqrtf(red[0] * (1.f/DMODEL) + 1e-5f);

    float* orow = out + (long)r*DMODEL;
    for (int i = tid; i < DMODEL; i += 256)
        orow[i] = g[i] * (row[i] - mean) * inv + b[i];
}

// ---------------- tiled SGEMM ----------------
// C[M,N] = A[M,K] @ B  (+bias) (+resid) (gelu)
// TRANSB=false: B row-major [K,N].  TRANSB=true: B row-major [N,K] (C = A @ B^T).
// EPI: 0 = bias only, 1 = bias + residual add, 2 = bias + exact GELU
#define BM 64
#define BN 64
#define BKK 16
template<bool TRANSB, int EPI>
__global__ void gemm_kernel(const float* __restrict__ A,
                            const float* __restrict__ B,
                            const float* __restrict__ bias,
                            const float* __restrict__ resid,
                            float* __restrict__ C,
                            int M, int N, int K) {
    __shared__ float As[BKK][BM+4];
    __shared__ float Bs[BKK][BN+4];
    int tid = threadIdx.x;          // 256 threads
    int tx  = tid & 15;             // N dir
    int ty  = tid >> 4;             // M dir
    int block_m = blockIdx.y * BM;
    int block_n = blockIdx.x * BN;

    float acc[4][4] = {};

    for (int k0 = 0; k0 < K; k0 += BKK) {
        // A tile: 64x16, stored transposed As[k][m]
        {
            int kk = tid & 15;
            int mm = tid >> 4;
            #pragma unroll
            for (int i = 0; i < 4; i++) {
                int m = mm + i*16;
                As[kk][m] = A[(long)(block_m + m)*K + k0 + kk];
            }
        }
        if (!TRANSB) {
            int nn  = tid & 63;
            int kk0 = tid >> 6;
            #pragma unroll
            for (int i = 0; i < 4; i++) {
                int kk = kk0 + i*4;
                int n  = block_n + nn;
                Bs[kk][nn] = (n < N) ? B[(long)(k0+kk)*N + n] : 0.f;
            }
        } else {
            int kk  = tid & 15;
            int nn0 = tid >> 4;
            #pragma unroll
            for (int i = 0; i < 4; i++) {
                int nn = nn0 + i*16;
                int n  = block_n + nn;
                Bs[kk][nn] = (n < N) ? B[(long)n*K + k0 + kk] : 0.f;
            }
        }
        __syncthreads();

        #pragma unroll
        for (int kk = 0; kk < BKK; kk++) {
            float a[4], bb[4];
            #pragma unroll
            for (int i = 0; i < 4; i++) a[i]  = As[kk][ty*4 + i];
            #pragma unroll
            for (int j = 0; j < 4; j++) bb[j] = Bs[kk][tx*4 + j];
            #pragma unroll
            for (int i = 0; i < 4; i++)
                #pragma unroll
                for (int j = 0; j < 4; j++)
                    acc[i][j] += a[i] * bb[j];
        }
        __syncthreads();
    }

    #pragma unroll
    for (int i = 0; i < 4; i++) {
        int m = block_m + ty*4 + i;
        #pragma unroll
        for (int j = 0; j < 4; j++) {
            int n = block_n + tx*4 + j;
            if (n < N) {
                float v = acc[i][j];
                if (bias) v += bias[n];
                if (EPI == 1) v += resid[(long)m*N + n];
                if (EPI == 2) v = 0.5f * v * (1.f + erff(v * 0.70710678118654752f));
                C[(long)m*N + n] = v;
            }
        }
    }
}

// ---------------- attention: one block per (b, h, q-row) ----------------
__global__ void attention_kernel(const float* __restrict__ qkv,
                                 float* __restrict__ out) {
    __shared__ float sc[TOK];
    __shared__ float qs[HD];
    __shared__ float red[128];

    int bid = blockIdx.x;
    int q_row = bid & (TOK-1);
    int h     = (bid >> 10) % NHEAD;
    int b     = bid / (TOK*NHEAD);
    int tid   = threadIdx.x;   // 128 threads

    long row = (long)b*TOK + q_row;
    const float* qptr = qkv + row*D3 + h*HD;
    if (tid < HD) qs[tid] = qptr[tid];
    __syncthreads();

    int nk = q_row + 1;
    const float scale = 0.125f;   // 1/sqrt(64)

    for (int k = tid; k < nk; k += 128) {
        const float* kptr = qkv + ((long)b*TOK + k)*D3 + DMODEL + h*HD;
        float s = 0.f;
        #pragma unroll
        for (int d = 0; d < HD; d++) s += qs[d] * kptr[d];
        sc[k] = s * scale;
    }
    __syncthreads();

    // max
    float m = -INFINITY;
    for (int k = tid; k < nk; k += 128) m = fmaxf(m, sc[k]);
    red[tid] = m; __syncthreads();
    for (int off = 64; off > 0; off >>= 1) { if (tid < off) red[tid] = fmaxf(red[tid], red[tid+off]); __syncthreads(); }
    float mx = red[0]; __syncthreads();

    // exp + sum
    float s = 0.f;
    for (int k = tid; k < nk; k += 128) { float e = expf(sc[k] - mx); sc[k] = e; s += e; }
    red[tid] = s; __syncthreads();
    for (int off = 64; off > 0; off >>= 1) { if (tid < off) red[tid] += red[tid+off]; __syncthreads(); }
    float inv = 1.f / red[0]; __syncthreads();

    // out[d] = sum_k p_k * v[k][d], split k across two halves of the block
    int d    = tid & 63;
    int half = tid >> 6;
    float acc = 0.f;
    for (int k = half; k < nk; k += 2) {
        acc += sc[k] * qkv[((long)b*TOK + k)*D3 + 2*DMODEL + h*HD + d];
    }
    red[tid] = acc; __syncthreads();
    if (half == 0)
        out[row*DMODEL + h*HD + d] = (red[tid] + red[tid + 64]) * inv;
}

// ---------------- launcher ----------------
extern "C" void kernel_launch(void* const* d_in, const int* in_sizes, int n_in,
                              void* d_out, int out_size) {
    const int*   ids    = (const int*)  d_in[0];
    const float* wte    = (const float*)d_in[1];
    const float* wpe    = (const float*)d_in[2];
    const float* ln1_g  = (const float*)d_in[3];
    const float* ln1_b  = (const float*)d_in[4];
    const float* attn_w = (const float*)d_in[5];
    const float* attn_b = (const float*)d_in[6];
    const float* proj_w = (const float*)d_in[7];
    const float* proj_b = (const float*)d_in[8];
    const float* ln2_g  = (const float*)d_in[9];
    const float* ln2_b  = (const float*)d_in[10];
    const float* fc_w   = (const float*)d_in[11];
    const float* fc_b   = (const float*)d_in[12];
    const float* out_w  = (const float*)d_in[13];
    const float* out_b  = (const float*)d_in[14];
    const float* lnf_g  = (const float*)d_in[15];
    const float* lnf_b  = (const float*)d_in[16];
    float* logits = (float*)d_out;

    float *px, *ph, *pqkv, *pattn, *pmlp;
    cudaGetSymbolAddress((void**)&px,    g_x);
    cudaGetSymbolAddress((void**)&ph,    g_h);
    cudaGetSymbolAddress((void**)&pqkv,  g_qkv);
    cudaGetSymbolAddress((void**)&pattn, g_attn);
    cudaGetSymbolAddress((void**)&pmlp,  g_mlp);

    embed_kernel<<<(ROWS*DMODEL + 255)/256, 256>>>(ids, wte, wpe, px);

    for (int l = 0; l < NLAYER; l++) {
        // --- attention block ---
        layernorm_kernel<<<ROWS, 256>>>(px, ln1_g + l*DMODEL, ln1_b + l*DMODEL, ph);
        gemm_kernel<false,0><<<dim3(D3/BN, ROWS/BM), 256>>>(
            ph, attn_w + (long)l*DMODEL*D3, attn_b + l*D3, nullptr, pqkv,
            ROWS, D3, DMODEL);
        attention_kernel<<<BATCH*NHEAD*TOK, 128>>>(pqkv, pattn);
        gemm_kernel<false,1><<<dim3(DMODEL/BN, ROWS/BM), 256>>>(
            pattn, proj_w + (long)l*DMODEL*DMODEL, proj_b + l*DMODEL, px, px,
            ROWS, DMODEL, DMODEL);
        // --- mlp block ---
        layernorm_kernel<<<ROWS, 256>>>(px, ln2_g + l*DMODEL, ln2_b + l*DMODEL, ph);
        gemm_kernel<false,2><<<dim3(D4/BN, ROWS/BM), 256>>>(
            ph, fc_w + (long)l*DMODEL*D4, fc_b + l*D4, nullptr, pmlp,
            ROWS, D4, DMODEL);
        gemm_kernel<false,1><<<dim3(DMODEL/BN, ROWS/BM), 256>>>(
            pmlp, out_w + (long)l*D4*DMODEL, out_b + l*DMODEL, px, px,
            ROWS, DMODEL, D4);
    }

    layernorm_kernel<<<ROWS, 256>>>(px, lnf_g, lnf_b, ph);
    gemm_kernel<true,0><<<dim3((VOCAB + BN - 1)/BN, ROWS/BM), 256>>>(
        ph, wte, nullptr, nullptr, logits,
        ROWS, VOCAB, DMODEL);
}

// round 4
// speedup vs baseline: 1.4801x; 1.4801x over previous
#include <cuda_runtime.h>
#include <cuda_bf16.h>
#include <math.h>
#include <stdint.h>

// ---------------- problem constants ----------------
#define BATCH 2
#define TOK   1024
#define ROWS  (BATCH*TOK)   // 2048
#define DMODEL 768
#define NHEAD 12
#define HD    64
#define NLAYER 4
#define VOCAB 50257
#define D3    (3*DMODEL)    // 2304
#define D4    (4*DMODEL)    // 3072

// ---------------- scratch (static device allocations) ----------------
__device__ float g_x   [ROWS*DMODEL];
__device__ float g_h   [ROWS*DMODEL];
__device__ float g_qkv [ROWS*D3];
__device__ float g_attn[ROWS*DMODEL];
__device__ float g_mlp [ROWS*D4];

// ---------------- embedding ----------------
__global__ void embed_kernel(const int* __restrict__ ids,
                             const float* __restrict__ wte,
                             const float* __restrict__ wpe,
                             float* __restrict__ x) {
    int idx = blockIdx.x * blockDim.x + threadIdx.x;
    if (idx >= ROWS*DMODEL) return;
    int row = idx / DMODEL;
    int d   = idx - row*DMODEL;
    int t   = row % TOK;
    x[idx] = wte[(long)ids[row]*DMODEL + d] + wpe[t*DMODEL + d];
}

// ---------------- layernorm (one block per row) ----------------
__global__ void layernorm_kernel(const float* __restrict__ x,
                                 const float* __restrict__ g,
                                 const float* __restrict__ b,
                                 float* __restrict__ out) {
    __shared__ float row[DMODEL];
    __shared__ float red[256];
    int r = blockIdx.x;
    int tid = threadIdx.x;
    const float* xr = x + (long)r*DMODEL;

    float s = 0.f;
    for (int i = tid; i < DMODEL; i += 256) { float v = xr[i]; row[i] = v; s += v; }
    red[tid] = s; __syncthreads();
    for (int off = 128; off > 0; off >>= 1) { if (tid < off) red[tid] += red[tid+off]; __syncthreads(); }
    float mean = red[0] * (1.f/DMODEL);
    __syncthreads();

    float vs = 0.f;
    for (int i = tid; i < DMODEL; i += 256) { float d = row[i] - mean; vs += d*d; }
    red[tid] = vs; __syncthreads();
    for (int off = 128; off > 0; off >>= 1) { if (tid < off) red[tid] += red[tid+off]; __syncthreads(); }
    float inv = rsqrtf(red[0] * (1.f/DMODEL) + 1e-5f);

    float* orow = out + (long)r*DMODEL;
    for (int i = tid; i < DMODEL; i += 256)
        orow[i] = g[i] * (row[i] - mean) * inv + b[i];
}

// ---------------- TF32 tensor-core GEMM ----------------
// C[M,N] = A[M,K] @ B  (+bias) (+resid) (gelu), fp32 accumulate, tf32 inputs.
// TRANSB=false: B row-major [K,N].  TRANSB=true: B row-major [N,K] (C = A @ B^T).
// EPI: 0 = bias only, 1 = bias + residual add, 2 = bias + exact GELU
//
// Block tile 128x64, 8 warps (4x2), warp tile 32x32, BK=32.
// Double-buffered smem with register staging.

__device__ __forceinline__ float to_tf32(float x) {
    uint32_t u;
    asm("cvt.rna.tf32.f32 %0, %1;" : "=r"(u) : "f"(x));
    return __uint_as_float(u);
}

__device__ __forceinline__ void mma_tf32(float* c, const uint32_t* a,
                                         uint32_t b0, uint32_t b1) {
    asm volatile(
        "mma.sync.aligned.m16n8k8.row.col.f32.tf32.tf32.f32 "
        "{%0,%1,%2,%3}, {%4,%5,%6,%7}, {%8,%9}, {%0,%1,%2,%3};"
        : "+f"(c[0]), "+f"(c[1]), "+f"(c[2]), "+f"(c[3])
        : "r"(a[0]), "r"(a[1]), "r"(a[2]), "r"(a[3]), "r"(b0), "r"(b1));
}

#define GBM 128
#define GBN 64
#define GBK 32
#define ASTRIDE 36                  // GBK + 4: conflict-free A/B^T fragment loads
#define ABUF    (GBM*ASTRIDE)       // 4608 floats per buffer

template<bool TRANSB, int EPI>
__global__ void __launch_bounds__(256)
gemm_tc(const float* __restrict__ A,
        const float* __restrict__ B,
        const float* __restrict__ bias,
        const float* __restrict__ resid,
        float* __restrict__ C,
        int M, int N, int K) {
    constexpr int BSTRIDE = TRANSB ? (GBK + 4) : (GBN + 4);     // 36 : 68
    constexpr int BBUF    = TRANSB ? (GBN * (GBK + 4)) : (GBK * (GBN + 4)); // 2304 : 2176

    extern __shared__ float smem[];
    float* As = smem;               // 2 * ABUF
    float* Bs = smem + 2*ABUF;      // 2 * BBUF

    const int tid  = threadIdx.x;
    const int lane = tid & 31;
    const int warp = tid >> 5;
    const int wm   = warp >> 1;     // 0..3 (M)
    const int wn   = warp & 1;      // 0..1 (N)
    const int bm   = blockIdx.y * GBM;
    const int bn   = blockIdx.x * GBN;

    float acc[2][4][4];
    #pragma unroll
    for (int i = 0; i < 2; i++)
        #pragma unroll
        for (int j = 0; j < 4; j++)
            #pragma unroll
            for (int k = 0; k < 4; k++) acc[i][j][k] = 0.f;

    float4 ra[4];
    float4 rb[2];

    // global -> regs
    auto loadA = [&](int k0) {
        #pragma unroll
        for (int p = 0; p < 4; p++) {
            int r = (tid >> 3) + p*32;
            int c = (tid & 7) * 4;
            ra[p] = *(const float4*)(A + (long)(bm + r)*K + k0 + c);
        }
    };
    auto loadB = [&](int k0) {
        if (!TRANSB) {
            #pragma unroll
            for (int p = 0; p < 2; p++) {
                int kk = (tid >> 4) + p*16;
                int nn = (tid & 15) * 4;
                rb[p] = *(const float4*)(B + (long)(k0 + kk)*N + bn + nn);
            }
        } else {
            #pragma unroll
            for (int p = 0; p < 2; p++) {
                int nn = (tid >> 3) + p*32;
                int kc = (tid & 7) * 4;
                int n  = bn + nn;
                if (n < N) rb[p] = *(const float4*)(B + (long)n*K + k0 + kc);
                else       rb[p] = make_float4(0.f, 0.f, 0.f, 0.f);
            }
        }
    };
    // regs -> smem (with tf32 rounding)
    auto storeTile = [&](int buf) {
        float* a = As + buf*ABUF;
        #pragma unroll
        for (int p = 0; p < 4; p++) {
            int r = (tid >> 3) + p*32;
            int c = (tid & 7) * 4;
            float* dst = a + r*ASTRIDE + c;
            dst[0] = to_tf32(ra[p].x); dst[1] = to_tf32(ra[p].y);
            dst[2] = to_tf32(ra[p].z); dst[3] = to_tf32(ra[p].w);
        }
        float* bsh = Bs + buf*BBUF;
        if (!TRANSB) {
            #pragma unroll
            for (int p = 0; p < 2; p++) {
                int kk = (tid >> 4) + p*16;
                int nn = (tid & 15) * 4;
                float* dst = bsh + kk*BSTRIDE + nn;
                dst[0] = to_tf32(rb[p].x); dst[1] = to_tf32(rb[p].y);
                dst[2] = to_tf32(rb[p].z); dst[3] = to_tf32(rb[p].w);
            }
        } else {
            #pragma unroll
            for (int p = 0; p < 2; p++) {
                int nn = (tid >> 3) + p*32;
                int kc = (tid & 7) * 4;
                float* dst = bsh + nn*BSTRIDE + kc;
                dst[0] = to_tf32(rb[p].x); dst[1] = to_tf32(rb[p].y);
                dst[2] = to_tf32(rb[p].z); dst[3] = to_tf32(rb[p].w);
            }
        }
    };
    // mainloop compute on one smem buffer
    auto compute = [&](int buf) {
        const float* a   = As + buf*ABUF;
        const float* bsh = Bs + buf*BBUF;
        #pragma unroll
        for (int ks = 0; ks < 4; ks++) {
            const int k = ks*8;
            uint32_t af[2][4];
            #pragma unroll
            for (int mt = 0; mt < 2; mt++) {
                int m  = wm*32 + mt*16 + (lane >> 2);
                int kc = k + (lane & 3);
                af[mt][0] = __float_as_uint(a[m*ASTRIDE + kc]);
                af[mt][1] = __float_as_uint(a[(m + 8)*ASTRIDE + kc]);
                af[mt][2] = __float_as_uint(a[m*ASTRIDE + kc + 4]);
                af[mt][3] = __float_as_uint(a[(m + 8)*ASTRIDE + kc + 4]);
            }
            #pragma unroll
            for (int nt = 0; nt < 4; nt++) {
                int n = wn*32 + nt*8 + (lane >> 2);
                uint32_t b0, b1;
                if (!TRANSB) {
                    b0 = __float_as_uint(bsh[(k +     (lane & 3))*BSTRIDE + n]);
                    b1 = __float_as_uint(bsh[(k + 4 + (lane & 3))*BSTRIDE + n]);
                } else {
                    b0 = __float_as_uint(bsh[n*BSTRIDE + k +     (lane & 3)]);
                    b1 = __float_as_uint(bsh[n*BSTRIDE + k + 4 + (lane & 3)]);
                }
                mma_tf32(acc[0][nt], af[0], b0, b1);
                mma_tf32(acc[1][nt], af[1], b0, b1);
            }
        }
    };

    const int NIT = K / GBK;
    loadA(0); loadB(0);
    storeTile(0);
    __syncthreads();

    for (int it = 0; it < NIT; ++it) {
        int cur = it & 1;
        if (it + 1 < NIT) { loadA((it + 1)*GBK); loadB((it + 1)*GBK); }
        compute(cur);
        if (it + 1 < NIT) {
            storeTile(1 - cur);
            __syncthreads();
        }
    }

    // epilogue
    #pragma unroll
    for (int mt = 0; mt < 2; mt++) {
        #pragma unroll
        for (int nt = 0; nt < 4; nt++) {
            int row0 = bm + wm*32 + mt*16 + (lane >> 2);
            int col0 = bn + wn*32 + nt*8 + (lane & 3)*2;
            #pragma unroll
            for (int h = 0; h < 2; h++) {        // rows row0, row0+8
                int m = row0 + h*8;
                #pragma unroll
                for (int j = 0; j < 2; j++) {    // cols col0, col0+1
                    int n = col0 + j;
                    if (n < N) {
                        float v = acc[mt][nt][h*2 + j];
                        if (bias) v += bias[n];
                        if (EPI == 1) v += resid[(long)m*N + n];
                        if (EPI == 2) v = 0.5f * v * (1.f + erff(v * 0.70710678118654752f));
                        C[(long)m*N + n] = v;
                    }
                }
            }
        }
    }
}

// ---------------- attention: one block per (b, h, q-row) ----------------
__global__ void attention_kernel(const float* __restrict__ qkv,
                                 float* __restrict__ out) {
    __shared__ float sc[TOK];
    __shared__ float qs[HD];
    __shared__ float red[128];

    int bid = blockIdx.x;
    int q_row = bid & (TOK-1);
    int h     = (bid >> 10) % NHEAD;
    int b     = bid / (TOK*NHEAD);
    int tid   = threadIdx.x;   // 128 threads

    long row = (long)b*TOK + q_row;
    const float* qptr = qkv + row*D3 + h*HD;
    if (tid < HD) qs[tid] = qptr[tid];
    __syncthreads();

    int nk = q_row + 1;
    const float scale = 0.125f;   // 1/sqrt(64)

    for (int k = tid; k < nk; k += 128) {
        const float* kptr = qkv + ((long)b*TOK + k)*D3 + DMODEL + h*HD;
        float s = 0.f;
        #pragma unroll
        for (int d = 0; d < HD; d++) s += qs[d] * kptr[d];
        sc[k] = s * scale;
    }
    __syncthreads();

    // max
    float m = -INFINITY;
    for (int k = tid; k < nk; k += 128) m = fmaxf(m, sc[k]);
    red[tid] = m; __syncthreads();
    for (int off = 64; off > 0; off >>= 1) { if (tid < off) red[tid] = fmaxf(red[tid], red[tid+off]); __syncthreads(); }
    float mx = red[0]; __syncthreads();

    // exp + sum
    float s = 0.f;
    for (int k = tid; k < nk; k += 128) { float e = expf(sc[k] - mx); sc[k] = e; s += e; }
    red[tid] = s; __syncthreads();
    for (int off = 64; off > 0; off >>= 1) { if (tid < off) red[tid] += red[tid+off]; __syncthreads(); }
    float inv = 1.f / red[0]; __syncthreads();

    // out[d] = sum_k p_k * v[k][d], split k across two halves of the block
    int d    = tid & 63;
    int half = tid >> 6;
    float acc = 0.f;
    for (int k = half; k < nk; k += 2) {
        acc += sc[k] * qkv[((long)b*TOK + k)*D3 + 2*DMODEL + h*HD + d];
    }
    red[tid] = acc; __syncthreads();
    if (half == 0)
        out[row*DMODEL + h*HD + d] = (red[tid] + red[tid + 64]) * inv;
}

// ---------------- launcher ----------------
extern "C" void kernel_launch(void* const* d_in, const int* in_sizes, int n_in,
                              void* d_out, int out_size) {
    const int*   ids    = (const int*)  d_in[0];
    const float* wte    = (const float*)d_in[1];
    const float* wpe    = (const float*)d_in[2];
    const float* ln1_g  = (const float*)d_in[3];
    const float* ln1_b  = (const float*)d_in[4];
    const float* attn_w = (const float*)d_in[5];
    const float* attn_b = (const float*)d_in[6];
    const float* proj_w = (const float*)d_in[7];
    const float* proj_b = (const float*)d_in[8];
    const float* ln2_g  = (const float*)d_in[9];
    const float* ln2_b  = (const float*)d_in[10];
    const float* fc_w   = (const float*)d_in[11];
    const float* fc_b   = (const float*)d_in[12];
    const float* out_w  = (const float*)d_in[13];
    const float* out_b  = (const float*)d_in[14];
    const float* lnf_g  = (const float*)d_in[15];
    const float* lnf_b  = (const float*)d_in[16];
    float* logits = (float*)d_out;

    float *px, *ph, *pqkv, *pattn, *pmlp;
    cudaGetSymbolAddress((void**)&px,    g_x);
    cudaGetSymbolAddress((void**)&ph,    g_h);
    cudaGetSymbolAddress((void**)&pqkv,  g_qkv);
    cudaGetSymbolAddress((void**)&pattn, g_attn);
    cudaGetSymbolAddress((void**)&pmlp,  g_mlp);

    // dynamic smem sizes (exceed 48KB static limit)
    const int SMEM_N = (2*ABUF + 2*(GBK*(GBN+4))) * 4;   // 54272 bytes
    const int SMEM_T = (2*ABUF + 2*(GBN*(GBK+4))) * 4;   // 55296 bytes
    cudaFuncSetAttribute(gemm_tc<false,0>, cudaFuncAttributeMaxDynamicSharedMemorySize, SMEM_N);
    cudaFuncSetAttribute(gemm_tc<false,1>, cudaFuncAttributeMaxDynamicSharedMemorySize, SMEM_N);
    cudaFuncSetAttribute(gemm_tc<false,2>, cudaFuncAttributeMaxDynamicSharedMemorySize, SMEM_N);
    cudaFuncSetAttribute(gemm_tc<true,0>,  cudaFuncAttributeMaxDynamicSharedMemorySize, SMEM_T);

    embed_kernel<<<(ROWS*DMODEL + 255)/256, 256>>>(ids, wte, wpe, px);

    for (int l = 0; l < NLAYER; l++) {
        // --- attention block ---
        layernorm_kernel<<<ROWS, 256>>>(px, ln1_g + l*DMODEL, ln1_b + l*DMODEL, ph);
        gemm_tc<false,0><<<dim3(D3/GBN, ROWS/GBM), 256, SMEM_N>>>(
            ph, attn_w + (long)l*DMODEL*D3, attn_b + l*D3, nullptr, pqkv,
            ROWS, D3, DMODEL);
        attention_kernel<<<BATCH*NHEAD*TOK, 128>>>(pqkv, pattn);
        gemm_tc<false,1><<<dim3(DMODEL/GBN, ROWS/GBM), 256, SMEM_N>>>(
            pattn, proj_w + (long)l*DMODEL*DMODEL, proj_b + l*DMODEL, px, px,
            ROWS, DMODEL, DMODEL);
        // --- mlp block ---
        layernorm_kernel<<<ROWS, 256>>>(px, ln2_g + l*DMODEL, ln2_b + l*DMODEL, ph);
        gemm_tc<false,2><<<dim3(D4/GBN, ROWS/GBM), 256, SMEM_N>>>(
            ph, fc_w + (long)l*DMODEL*D4, fc_b + l*D4, nullptr, pmlp,
            ROWS, D4, DMODEL);
        gemm_tc<false,1><<<dim3(DMODEL/GBN, ROWS/GBM), 256, SMEM_N>>>(
            pmlp, out_w + (long)l*D4*DMODEL, out_b + l*DMODEL, px, px,
            ROWS, DMODEL, D4);
    }

    layernorm_kernel<<<ROWS, 256>>>(px, lnf_g, lnf_b, ph);
    gemm_tc<true,0><<<dim3((VOCAB + GBN - 1)/GBN, ROWS/GBM), 256, SMEM_T>>>(
        ph, wte, nullptr, nullptr, logits,
        ROWS, VOCAB, DMODEL);
}

// round 5
// speedup vs baseline: 4.5405x; 3.0678x over previous
#include <cuda_runtime.h>
#include <cuda_bf16.h>
#include <math.h>
#include <stdint.h>

// ---------------- problem constants ----------------
#define BATCH 2
#define TOK   1024
#define ROWS  (BATCH*TOK)   // 2048
#define DMODEL 768
#define NHEAD 12
#define HD    64
#define NLAYER 4
#define VOCAB 50257
#define D3    (3*DMODEL)    // 2304
#define D4    (4*DMODEL)    // 3072

// ---------------- scratch (static device allocations) ----------------
__device__ float g_x   [ROWS*DMODEL];
__device__ float g_h   [ROWS*DMODEL];
__device__ float g_qkv [ROWS*D3];
__device__ float g_attn[ROWS*DMODEL];
__device__ float g_mlp [ROWS*D4];
__device__ float g_kt  [BATCH*NHEAD*HD*TOK];   // K transposed: [b,h,d,t]

// ---------------- embedding ----------------
__global__ void embed_kernel(const int* __restrict__ ids,
                             const float* __restrict__ wte,
                             const float* __restrict__ wpe,
                             float* __restrict__ x) {
    int idx = blockIdx.x * blockDim.x + threadIdx.x;
    if (idx >= ROWS*DMODEL) return;
    int row = idx / DMODEL;
    int d   = idx - row*DMODEL;
    int t   = row % TOK;
    x[idx] = wte[(long)ids[row]*DMODEL + d] + wpe[t*DMODEL + d];
}

// ---------------- layernorm (one block per row) ----------------
__global__ void layernorm_kernel(const float* __restrict__ x,
                                 const float* __restrict__ g,
                                 const float* __restrict__ b,
                                 float* __restrict__ out) {
    __shared__ float row[DMODEL];
    __shared__ float red[256];
    int r = blockIdx.x;
    int tid = threadIdx.x;
    const float* xr = x + (long)r*DMODEL;

    float s = 0.f;
    for (int i = tid; i < DMODEL; i += 256) { float v = xr[i]; row[i] = v; s += v; }
    red[tid] = s; __syncthreads();
    for (int off = 128; off > 0; off >>= 1) { if (tid < off) red[tid] += red[tid+off]; __syncthreads(); }
    float mean = red[0] * (1.f/DMODEL);
    __syncthreads();

    float vs = 0.f;
    for (int i = tid; i < DMODEL; i += 256) { float d = row[i] - mean; vs += d*d; }
    red[tid] = vs; __syncthreads();
    for (int off = 128; off > 0; off >>= 1) { if (tid < off) red[tid] += red[tid+off]; __syncthreads(); }
    float inv = rsqrtf(red[0] * (1.f/DMODEL) + 1e-5f);

    float* orow = out + (long)r*DMODEL;
    for (int i = tid; i < DMODEL; i += 256)
        orow[i] = g[i] * (row[i] - mean) * inv + b[i];
}

// ---------------- TF32 tensor-core GEMM, cp.async 3-stage ----------------
// C[M,N] = A[M,K] @ B (+bias) (+resid) (gelu), fp32 accumulate, tf32 inputs.
// TRANSB=false: B row-major [K,N] (N must be multiple of 128).
// TRANSB=true : B row-major [N,K] (C = A @ B^T), N arbitrary.
// EPI: 0 = bias only, 1 = bias + residual add, 2 = bias + exact GELU
// Block 128x128x32, 256 threads, 8 warps as 2(M) x 4(N), warp tile 64x32.

__device__ __forceinline__ uint32_t ld_tf32(const float* p) {
    uint32_t u; asm("cvt.rna.tf32.f32 %0, %1;" : "=r"(u) : "f"(*p)); return u;
}

__device__ __forceinline__ void mma_tf32(float* c, const uint32_t* a,
                                         uint32_t b0, uint32_t b1) {
    asm volatile(
        "mma.sync.aligned.m16n8k8.row.col.f32.tf32.tf32.f32 "
        "{%0,%1,%2,%3}, {%4,%5,%6,%7}, {%8,%9}, {%0,%1,%2,%3};"
        : "+f"(c[0]), "+f"(c[1]), "+f"(c[2]), "+f"(c[3])
        : "r"(a[0]), "r"(a[1]), "r"(a[2]), "r"(a[3]), "r"(b0), "r"(b1));
}

__device__ __forceinline__ void cp_async16(float* smem_ptr, const float* gptr) {
    uint32_t saddr = (uint32_t)__cvta_generic_to_shared(smem_ptr);
    asm volatile("cp.async.cg.shared.global [%0], [%1], 16;\n" :: "r"(saddr), "l"(gptr));
}
__device__ __forceinline__ void cp_commit() { asm volatile("cp.async.commit_group;\n"); }
template<int N> __device__ __forceinline__ void cp_wait() {
    asm volatile("cp.async.wait_group %0;\n" :: "n"(N));
}

#define GBM 128
#define GBN 128
#define GBK 32
#define STAGES 3
#define ASTR 36                       // floats; 144B rows, conflict-free frags
#define A_SZ (GBM*ASTR)               // 4608 floats / stage

template<bool TRANSB, int EPI>
__global__ void __launch_bounds__(256)
gemm_tc(const float* __restrict__ A,
        const float* __restrict__ B,
        const float* __restrict__ bias,
        const float* __restrict__ resid,
        float* __restrict__ C,
        int M, int N, int K) {
    constexpr int BSTR = TRANSB ? 36 : 136;               // floats
    constexpr int B_SZ = TRANSB ? (GBN*36) : (GBK*136);   // 4608 : 4352

    extern __shared__ float smem[];
    float* As = smem;                     // STAGES * A_SZ
    float* Bs = smem + STAGES*A_SZ;       // STAGES * B_SZ

    const int tid  = threadIdx.x;
    const int lane = tid & 31;
    const int warp = tid >> 5;
    const int wm   = warp >> 2;     // 0..1  (64-row M slab)
    const int wn   = warp & 3;      // 0..3  (32-col N slab)
    const int bm   = blockIdx.y * GBM;
    const int bn   = blockIdx.x * GBN;

    float acc[4][4][4];
    #pragma unroll
    for (int i = 0; i < 4; i++)
        #pragma unroll
        for (int j = 0; j < 4; j++)
            #pragma unroll
            for (int k = 0; k < 4; k++) acc[i][j][k] = 0.f;

    auto issue_load = [&](int stage, int k0) {
        float* a = As + stage*A_SZ;
        // A tile: 128 x 32
        #pragma unroll
        for (int p = 0; p < 4; p++) {
            int r = (tid >> 3) + p*32;
            int c = (tid & 7) * 4;
            cp_async16(a + r*ASTR + c, A + (long)(bm + r)*K + k0 + c);
        }
        float* bsh = Bs + stage*B_SZ;
        if (!TRANSB) {
            // B tile: 32 x 128, K-major
            int kk = tid >> 3;
            #pragma unroll
            for (int p = 0; p < 4; p++) {
                int c = ((tid & 7) + p*8) * 4;
                cp_async16(bsh + kk*BSTR + c, B + (long)(k0 + kk)*N + bn + c);
            }
        } else {
            // B tile: 128 x 32, N-major (rows clamped; garbage cols masked in epilogue)
            #pragma unroll
            for (int p = 0; p < 4; p++) {
                int nn = (tid >> 3) + p*32;
                int n  = bn + nn; if (n > N-1) n = N-1;
                int c  = (tid & 7) * 4;
                cp_async16(bsh + nn*BSTR + c, B + (long)n*K + k0 + c);
            }
        }
    };

    auto compute = [&](int stage) {
        const float* a   = As + stage*A_SZ;
        const float* bsh = Bs + stage*B_SZ;
        #pragma unroll
        for (int ks = 0; ks < 4; ks++) {
            const int k = ks*8;
            uint32_t af[4][4];
            #pragma unroll
            for (int mt = 0; mt < 4; mt++) {
                int m  = wm*64 + mt*16 + (lane >> 2);
                int kc = k + (lane & 3);
                af[mt][0] = ld_tf32(a + m*ASTR + kc);
                af[mt][1] = ld_tf32(a + (m + 8)*ASTR + kc);
                af[mt][2] = ld_tf32(a + m*ASTR + kc + 4);
                af[mt][3] = ld_tf32(a + (m + 8)*ASTR + kc + 4);
            }
            uint32_t bf[4][2];
            #pragma unroll
            for (int nt = 0; nt < 4; nt++) {
                int n = wn*32 + nt*8 + (lane >> 2);
                if (!TRANSB) {
                    bf[nt][0] = ld_tf32(bsh + (k +     (lane & 3))*BSTR + n);
                    bf[nt][1] = ld_tf32(bsh + (k + 4 + (lane & 3))*BSTR + n);
                } else {
                    bf[nt][0] = ld_tf32(bsh + n*BSTR + k +     (lane & 3));
                    bf[nt][1] = ld_tf32(bsh + n*BSTR + k + 4 + (lane & 3));
                }
            }
            #pragma unroll
            for (int mt = 0; mt < 4; mt++)
                #pragma unroll
                for (int nt = 0; nt < 4; nt++)
                    mma_tf32(acc[mt][nt], af[mt], bf[nt][0], bf[nt][1]);
        }
    };

    const int NIT = K / GBK;
    #pragma unroll
    for (int s = 0; s < STAGES-1; s++) { issue_load(s, s*GBK); cp_commit(); }

    for (int it = 0; it < NIT; ++it) {
        cp_wait<STAGES-2>();
        __syncthreads();
        int nxt = it + STAGES - 1;
        if (nxt < NIT) issue_load(nxt % STAGES, nxt*GBK);
        cp_commit();
        compute(it % STAGES);
    }

    // epilogue
    #pragma unroll
    for (int mt = 0; mt < 4; mt++) {
        #pragma unroll
        for (int nt = 0; nt < 4; nt++) {
            int row0 = bm + wm*64 + mt*16 + (lane >> 2);
            int col0 = bn + wn*32 + nt*8 + (lane & 3)*2;
            #pragma unroll
            for (int h = 0; h < 2; h++) {
                int m = row0 + h*8;
                #pragma unroll
                for (int j = 0; j < 2; j++) {
                    int n = col0 + j;
                    if (n < N) {
                        float v = acc[mt][nt][h*2 + j];
                        if (bias) v += bias[n];
                        if (EPI == 1) v += resid[(long)m*N + n];
                        if (EPI == 2) v = 0.5f * v * (1.f + erff(v * 0.70710678118654752f));
                        C[(long)m*N + n] = v;
                    }
                }
            }
        }
    }
}

// ---------------- K transpose: qkv K-section -> Kt[b,h,d,t] ----------------
__global__ void transpose_k_kernel(const float* __restrict__ qkv,
                                   float* __restrict__ kt) {
    __shared__ float tile[32][33];
    int bh = blockIdx.z;                 // b*NHEAD + h
    int b  = bh / NHEAD, h = bh % NHEAD;
    int t0 = blockIdx.x * 32, d0 = blockIdx.y * 32;
    int tx = threadIdx.x & 31, ty = threadIdx.x >> 5;    // 256 thr: ty 0..7

    #pragma unroll
    for (int i = ty; i < 32; i += 8)
        tile[i][tx] = qkv[((long)(b*TOK + t0 + i))*D3 + DMODEL + h*HD + d0 + tx];
    __syncthreads();
    #pragma unroll
    for (int i = ty; i < 32; i += 8)
        kt[((long)(bh*HD + d0 + i))*TOK + t0 + tx] = tile[tx][i];
}

// ---------------- attention: one block per (b, h, q-row) ----------------
// Scores read K from Kt[b,h,d,t] so lanes access consecutive t (coalesced).
__global__ void attention_kernel(const float* __restrict__ qkv,
                                 const float* __restrict__ kt,
                                 float* __restrict__ out) {
    __shared__ float sc[TOK];
    __shared__ float qs[HD];
    __shared__ float red[128];

    int bid = blockIdx.x;
    int q_row = bid & (TOK-1);
    int h     = (bid >> 10) % NHEAD;
    int b     = bid / (TOK*NHEAD);
    int tid   = threadIdx.x;   // 128 threads

    long row = (long)b*TOK + q_row;
    const float* qptr = qkv + row*D3 + h*HD;
    if (tid < HD) qs[tid] = qptr[tid];
    __syncthreads();

    int nk = q_row + 1;
    const float scale = 0.125f;   // 1/sqrt(64)
    const float* kbase = kt + (long)(b*NHEAD + h)*HD*TOK;

    for (int k = tid; k < nk; k += 128) {
        float s = 0.f;
        #pragma unroll
        for (int d = 0; d < HD; d++) s += qs[d] * kbase[d*TOK + k];
        sc[k] = s * scale;
    }
    __syncthreads();

    // max
    float m = -INFINITY;
    for (int k = tid; k < nk; k += 128) m = fmaxf(m, sc[k]);
    red[tid] = m; __syncthreads();
    for (int off = 64; off > 0; off >>= 1) { if (tid < off) red[tid] = fmaxf(red[tid], red[tid+off]); __syncthreads(); }
    float mx = red[0]; __syncthreads();

    // exp + sum
    float s = 0.f;
    for (int k = tid; k < nk; k += 128) { float e = expf(sc[k] - mx); sc[k] = e; s += e; }
    red[tid] = s; __syncthreads();
    for (int off = 64; off > 0; off >>= 1) { if (tid < off) red[tid] += red[tid+off]; __syncthreads(); }
    float inv = 1.f / red[0]; __syncthreads();

    // out[d] = sum_k p_k * v[k][d]  (coalesced across d)
    int d    = tid & 63;
    int half = tid >> 6;
    float acc = 0.f;
    for (int k = half; k < nk; k += 2) {
        acc += sc[k] * qkv[((long)b*TOK + k)*D3 + 2*DMODEL + h*HD + d];
    }
    red[tid] = acc; __syncthreads();
    if (half == 0)
        out[row*DMODEL + h*HD + d] = (red[tid] + red[tid + 64]) * inv;
}

// ---------------- launcher ----------------
extern "C" void kernel_launch(void* const* d_in, const int* in_sizes, int n_in,
                              void* d_out, int out_size) {
    const int*   ids    = (const int*)  d_in[0];
    const float* wte    = (const float*)d_in[1];
    const float* wpe    = (const float*)d_in[2];
    const float* ln1_g  = (const float*)d_in[3];
    const float* ln1_b  = (const float*)d_in[4];
    const float* attn_w = (const float*)d_in[5];
    const float* attn_b = (const float*)d_in[6];
    const float* proj_w = (const float*)d_in[7];
    const float* proj_b = (const float*)d_in[8];
    const float* ln2_g  = (const float*)d_in[9];
    const float* ln2_b  = (const float*)d_in[10];
    const float* fc_w   = (const float*)d_in[11];
    const float* fc_b   = (const float*)d_in[12];
    const float* out_w  = (const float*)d_in[13];
    const float* out_b  = (const float*)d_in[14];
    const float* lnf_g  = (const float*)d_in[15];
    const float* lnf_b  = (const float*)d_in[16];
    float* logits = (float*)d_out;

    float *px, *ph, *pqkv, *pattn, *pmlp, *pkt;
    cudaGetSymbolAddress((void**)&px,    g_x);
    cudaGetSymbolAddress((void**)&ph,    g_h);
    cudaGetSymbolAddress((void**)&pqkv,  g_qkv);
    cudaGetSymbolAddress((void**)&pattn, g_attn);
    cudaGetSymbolAddress((void**)&pmlp,  g_mlp);
    cudaGetSymbolAddress((void**)&pkt,   g_kt);

    const int SMEM_N = (STAGES*A_SZ + STAGES*(GBK*136)) * 4;   // 107,520 B
    const int SMEM_T = (STAGES*A_SZ + STAGES*(GBN*36))  * 4;   // 110,592 B
    cudaFuncSetAttribute(gemm_tc<false,0>, cudaFuncAttributeMaxDynamicSharedMemorySize, SMEM_N);
    cudaFuncSetAttribute(gemm_tc<false,1>, cudaFuncAttributeMaxDynamicSharedMemorySize, SMEM_N);
    cudaFuncSetAttribute(gemm_tc<false,2>, cudaFuncAttributeMaxDynamicSharedMemorySize, SMEM_N);
    cudaFuncSetAttribute(gemm_tc<true,0>,  cudaFuncAttributeMaxDynamicSharedMemorySize, SMEM_T);

    embed_kernel<<<(ROWS*DMODEL + 255)/256, 256>>>(ids, wte, wpe, px);

    for (int l = 0; l < NLAYER; l++) {
        // --- attention block ---
        layernorm_kernel<<<ROWS, 256>>>(px, ln1_g + l*DMODEL, ln1_b + l*DMODEL, ph);
        gemm_tc<false,0><<<dim3(D3/GBN, ROWS/GBM), 256, SMEM_N>>>(
            ph, attn_w + (long)l*DMODEL*D3, attn_b + l*D3, nullptr, pqkv,
            ROWS, D3, DMODEL);
        transpose_k_kernel<<<dim3(TOK/32, HD/32, BATCH*NHEAD), 256>>>(pqkv, pkt);
        attention_kernel<<<BATCH*NHEAD*TOK, 128>>>(pqkv, pkt, pattn);
        gemm_tc<false,1><<<dim3(DMODEL/GBN, ROWS/GBM), 256, SMEM_N>>>(
            pattn, proj_w + (long)l*DMODEL*DMODEL, proj_b + l*DMODEL, px, px,
            ROWS, DMODEL, DMODEL);
        // --- mlp block ---
        layernorm_kernel<<<ROWS, 256>>>(px, ln2_g + l*DMODEL, ln2_b + l*DMODEL, ph);
        gemm_tc<false,2><<<dim3(D4/GBN, ROWS/GBM), 256, SMEM_N>>>(
            ph, fc_w + (long)l*DMODEL*D4, fc_b + l*D4, nullptr, pmlp,
            ROWS, D4, DMODEL);
        gemm_tc<false,1><<<dim3(DMODEL/GBN, ROWS/GBM), 256, SMEM_N>>>(
            pmlp, out_w + (long)l*D4*DMODEL, out_b + l*DMODEL, px, px,
            ROWS, DMODEL, D4);
    }

    layernorm_kernel<<<ROWS, 256>>>(px, lnf_g, lnf_b, ph);
    gemm_tc<true,0><<<dim3((VOCAB + GBN - 1)/GBN, ROWS/GBM), 256, SMEM_T>>>(
        ph, wte, nullptr, nullptr, logits,
        ROWS, VOCAB, DMODEL);
}

// round 6
// speedup vs baseline: 4.7027x; 1.0357x over previous
#include <cuda_runtime.h>
#include <cuda_bf16.h>
#include <math.h>
#include <stdint.h>

// ---------------- problem constants ----------------
#define BATCH 2
#define TOK   1024
#define ROWS  (BATCH*TOK)   // 2048
#define DMODEL 768
#define NHEAD 12
#define HD    64
#define NLAYER 4
#define VOCAB 50257
#define D3    (3*DMODEL)    // 2304
#define D4    (4*DMODEL)    // 3072

// ---------------- scratch (static device allocations) ----------------
__device__ float g_x   [ROWS*DMODEL];
__device__ float g_h   [ROWS*DMODEL];
__device__ float g_qkv [ROWS*D3];
__device__ float g_attn[ROWS*DMODEL];
__device__ float g_mlp [ROWS*D4];
__device__ float g_kt  [BATCH*NHEAD*HD*TOK];   // K transposed: [b,h,d,t]

// pre-rounded tf32 weight copies
__device__ float g_wqkv[NLAYER*DMODEL*D3];
__device__ float g_wproj[NLAYER*DMODEL*DMODEL];
__device__ float g_wfc [NLAYER*DMODEL*D4];
__device__ float g_wout[NLAYER*D4*DMODEL];
__device__ float g_wte [VOCAB*DMODEL];

__device__ __forceinline__ float rnd_tf32(float x) {
    uint32_t u; asm("cvt.rna.tf32.f32 %0, %1;" : "=r"(u) : "f"(x));
    return __uint_as_float(u);
}

// ---------------- tf32 pre-rounding copy ----------------
__global__ void round4_kernel(const float4* __restrict__ in,
                              float4* __restrict__ out, int n4) {
    for (int i = blockIdx.x*blockDim.x + threadIdx.x; i < n4;
         i += gridDim.x*blockDim.x) {
        float4 v = in[i];
        v.x = rnd_tf32(v.x); v.y = rnd_tf32(v.y);
        v.z = rnd_tf32(v.z); v.w = rnd_tf32(v.w);
        out[i] = v;
    }
}

// ---------------- embedding ----------------
__global__ void embed_kernel(const int* __restrict__ ids,
                             const float* __restrict__ wte,
                             const float* __restrict__ wpe,
                             float* __restrict__ x) {
    int idx = blockIdx.x * blockDim.x + threadIdx.x;
    if (idx >= ROWS*DMODEL) return;
    int row = idx / DMODEL;
    int d   = idx - row*DMODEL;
    int t   = row % TOK;
    x[idx] = wte[(long)ids[row]*DMODEL + d] + wpe[t*DMODEL + d];
}

// ---------------- layernorm (one block per row), tf32-rounded output ----------------
__global__ void layernorm_kernel(const float* __restrict__ x,
                                 const float* __restrict__ g,
                                 const float* __restrict__ b,
                                 float* __restrict__ out) {
    __shared__ float row[DMODEL];
    __shared__ float red[256];
    int r = blockIdx.x;
    int tid = threadIdx.x;
    const float* xr = x + (long)r*DMODEL;

    float s = 0.f;
    for (int i = tid; i < DMODEL; i += 256) { float v = xr[i]; row[i] = v; s += v; }
    red[tid] = s; __syncthreads();
    for (int off = 128; off > 0; off >>= 1) { if (tid < off) red[tid] += red[tid+off]; __syncthreads(); }
    float mean = red[0] * (1.f/DMODEL);
    __syncthreads();

    float vs = 0.f;
    for (int i = tid; i < DMODEL; i += 256) { float d = row[i] - mean; vs += d*d; }
    red[tid] = vs; __syncthreads();
    for (int off = 128; off > 0; off >>= 1) { if (tid < off) red[tid] += red[tid+off]; __syncthreads(); }
    float inv = rsqrtf(red[0] * (1.f/DMODEL) + 1e-5f);

    float* orow = out + (long)r*DMODEL;
    for (int i = tid; i < DMODEL; i += 256)
        orow[i] = rnd_tf32(g[i] * (row[i] - mean) * inv + b[i]);
}

// ---------------- TF32 tensor-core GEMM, cp.async 3-stage ----------------
// Inputs A and B must already be tf32-rounded. fp32 accumulate.
// TRANSB=false: B row-major [K,N] (N mult of 128). TRANSB=true: B [N,K].
// EPI: 0 = bias only, 1 = bias + residual add, 2 = bias + exact GELU (tf32-rounded out)
// Block 128x128x32, 256 threads, 8 warps as 2(M) x 4(N), warp tile 64x32.
// Grid: x = M blocks, y = N blocks (M-major rasterization for B reuse).

__device__ __forceinline__ void mma_tf32(float* c, const uint32_t* a,
                                         uint32_t b0, uint32_t b1) {
    asm volatile(
        "mma.sync.aligned.m16n8k8.row.col.f32.tf32.tf32.f32 "
        "{%0,%1,%2,%3}, {%4,%5,%6,%7}, {%8,%9}, {%0,%1,%2,%3};"
        : "+f"(c[0]), "+f"(c[1]), "+f"(c[2]), "+f"(c[3])
        : "r"(a[0]), "r"(a[1]), "r"(a[2]), "r"(a[3]), "r"(b0), "r"(b1));
}

__device__ __forceinline__ void cp_async16(float* smem_ptr, const float* gptr) {
    uint32_t saddr = (uint32_t)__cvta_generic_to_shared(smem_ptr);
    asm volatile("cp.async.cg.shared.global [%0], [%1], 16;\n" :: "r"(saddr), "l"(gptr));
}
__device__ __forceinline__ void cp_commit() { asm volatile("cp.async.commit_group;\n"); }
template<int N> __device__ __forceinline__ void cp_wait() {
    asm volatile("cp.async.wait_group %0;\n" :: "n"(N));
}

#define GBM 128
#define GBN 128
#define GBK 32
#define STAGES 3
#define ASTR 36
#define A_SZ (GBM*ASTR)               // 4608 floats / stage

template<bool TRANSB, int EPI>
__global__ void __launch_bounds__(256, 2)
gemm_tc(const float* __restrict__ A,
        const float* __restrict__ B,
        const float* __restrict__ bias,
        const float* __restrict__ resid,
        float* __restrict__ C,
        int M, int N, int K) {
    constexpr int BSTR = TRANSB ? 36 : 136;               // floats
    constexpr int B_SZ = TRANSB ? (GBN*36) : (GBK*136);   // 4608 : 4352

    extern __shared__ float smem[];
    float* As = smem;                     // STAGES * A_SZ
    float* Bs = smem + STAGES*A_SZ;       // STAGES * B_SZ

    const int tid  = threadIdx.x;
    const int lane = tid & 31;
    const int warp = tid >> 5;
    const int wm   = warp >> 2;     // 0..1  (64-row M slab)
    const int wn   = warp & 3;      // 0..3  (32-col N slab)
    const int bm   = blockIdx.x * GBM;    // M-major rasterization
    const int bn   = blockIdx.y * GBN;

    float acc[4][4][4];
    #pragma unroll
    for (int i = 0; i < 4; i++)
        #pragma unroll
        for (int j = 0; j < 4; j++)
            #pragma unroll
            for (int k = 0; k < 4; k++) acc[i][j][k] = 0.f;

    auto issue_load = [&](int stage, int k0) {
        float* a = As + stage*A_SZ;
        #pragma unroll
        for (int p = 0; p < 4; p++) {
            int r = (tid >> 3) + p*32;
            int c = (tid & 7) * 4;
            cp_async16(a + r*ASTR + c, A + (long)(bm + r)*K + k0 + c);
        }
        float* bsh = Bs + stage*B_SZ;
        if (!TRANSB) {
            int kk = tid >> 3;
            #pragma unroll
            for (int p = 0; p < 4; p++) {
                int c = ((tid & 7) + p*8) * 4;
                cp_async16(bsh + kk*BSTR + c, B + (long)(k0 + kk)*N + bn + c);
            }
        } else {
            #pragma unroll
            for (int p = 0; p < 4; p++) {
                int nn = (tid >> 3) + p*32;
                int n  = bn + nn; if (n > N-1) n = N-1;
                int c  = (tid & 7) * 4;
                cp_async16(bsh + nn*BSTR + c, B + (long)n*K + k0 + c);
            }
        }
    };

    auto compute = [&](int stage) {
        const float* a   = As + stage*A_SZ;
        const float* bsh = Bs + stage*B_SZ;
        #pragma unroll
        for (int ks = 0; ks < 4; ks++) {
            const int k = ks*8;
            uint32_t af[4][4];
            #pragma unroll
            for (int mt = 0; mt < 4; mt++) {
                int m  = wm*64 + mt*16 + (lane >> 2);
                int kc = k + (lane & 3);
                af[mt][0] = __float_as_uint(a[m*ASTR + kc]);
                af[mt][1] = __float_as_uint(a[(m + 8)*ASTR + kc]);
                af[mt][2] = __float_as_uint(a[m*ASTR + kc + 4]);
                af[mt][3] = __float_as_uint(a[(m + 8)*ASTR + kc + 4]);
            }
            uint32_t bf[4][2];
            #pragma unroll
            for (int nt = 0; nt < 4; nt++) {
                int n = wn*32 + nt*8 + (lane >> 2);
                if (!TRANSB) {
                    bf[nt][0] = __float_as_uint(bsh[(k +     (lane & 3))*BSTR + n]);
                    bf[nt][1] = __float_as_uint(bsh[(k + 4 + (lane & 3))*BSTR + n]);
                } else {
                    bf[nt][0] = __float_as_uint(bsh[n*BSTR + k +     (lane & 3)]);
                    bf[nt][1] = __float_as_uint(bsh[n*BSTR + k + 4 + (lane & 3)]);
                }
            }
            #pragma unroll
            for (int mt = 0; mt < 4; mt++)
                #pragma unroll
                for (int nt = 0; nt < 4; nt++)
                    mma_tf32(acc[mt][nt], af[mt], bf[nt][0], bf[nt][1]);
        }
    };

    const int NIT = K / GBK;
    #pragma unroll
    for (int s = 0; s < STAGES-1; s++) { issue_load(s, s*GBK); cp_commit(); }

    for (int it = 0; it < NIT; ++it) {
        cp_wait<STAGES-2>();
        __syncthreads();
        int nxt = it + STAGES - 1;
        if (nxt < NIT) issue_load(nxt % STAGES, nxt*GBK);
        cp_commit();
        compute(it % STAGES);
    }

    // epilogue
    #pragma unroll
    for (int mt = 0; mt < 4; mt++) {
        #pragma unroll
        for (int nt = 0; nt < 4; nt++) {
            int row0 = bm + wm*64 + mt*16 + (lane >> 2);
            int col0 = bn + wn*32 + nt*8 + (lane & 3)*2;
            #pragma unroll
            for (int h = 0; h < 2; h++) {
                int m = row0 + h*8;
                #pragma unroll
                for (int j = 0; j < 2; j++) {
                    int n = col0 + j;
                    if (n < N) {
                        float v = acc[mt][nt][h*2 + j];
                        if (bias) v += bias[n];
                        if (EPI == 1) v += resid[(long)m*N + n];
                        if (EPI == 2) v = rnd_tf32(0.5f * v * (1.f + erff(v * 0.70710678118654752f)));
                        C[(long)m*N + n] = v;
                    }
                }
            }
        }
    }
}

// ---------------- K transpose: qkv K-section -> Kt[b,h,d,t] ----------------
__global__ void transpose_k_kernel(const float* __restrict__ qkv,
                                   float* __restrict__ kt) {
    __shared__ float tile[32][33];
    int bh = blockIdx.z;                 // b*NHEAD + h
    int b  = bh / NHEAD, h = bh % NHEAD;
    int t0 = blockIdx.x * 32, d0 = blockIdx.y * 32;
    int tx = threadIdx.x & 31, ty = threadIdx.x >> 5;    // 256 thr: ty 0..7

    #pragma unroll
    for (int i = ty; i < 32; i += 8)
        tile[i][tx] = qkv[((long)(b*TOK + t0 + i))*D3 + DMODEL + h*HD + d0 + tx];
    __syncthreads();
    #pragma unroll
    for (int i = ty; i < 32; i += 8)
        kt[((long)(bh*HD + d0 + i))*TOK + t0 + tx] = tile[tx][i];
}

// ---------------- attention: one block per (b, h, q-row) ----------------
__global__ void attention_kernel(const float* __restrict__ qkv,
                                 const float* __restrict__ kt,
                                 float* __restrict__ out) {
    __shared__ float sc[TOK];
    __shared__ float qs[HD];
    __shared__ float red[128];

    int bid = blockIdx.x;
    int q_row = bid & (TOK-1);
    int h     = (bid >> 10) % NHEAD;
    int b     = bid / (TOK*NHEAD);
    int tid   = threadIdx.x;   // 128 threads

    long row = (long)b*TOK + q_row;
    const float* qptr = qkv + row*D3 + h*HD;
    if (tid < HD) qs[tid] = qptr[tid];
    __syncthreads();

    int nk = q_row + 1;
    const float scale = 0.125f;   // 1/sqrt(64)
    const float* kbase = kt + (long)(b*NHEAD + h)*HD*TOK;

    for (int k = tid; k < nk; k += 128) {
        float s = 0.f;
        #pragma unroll
        for (int d = 0; d < HD; d++) s += qs[d] * kbase[d*TOK + k];
        sc[k] = s * scale;
    }
    __syncthreads();

    float m = -INFINITY;
    for (int k = tid; k < nk; k += 128) m = fmaxf(m, sc[k]);
    red[tid] = m; __syncthreads();
    for (int off = 64; off > 0; off >>= 1) { if (tid < off) red[tid] = fmaxf(red[tid], red[tid+off]); __syncthreads(); }
    float mx = red[0]; __syncthreads();

    float s = 0.f;
    for (int k = tid; k < nk; k += 128) { float e = expf(sc[k] - mx); sc[k] = e; s += e; }
    red[tid] = s; __syncthreads();
    for (int off = 64; off > 0; off >>= 1) { if (tid < off) red[tid] += red[tid+off]; __syncthreads(); }
    float inv = 1.f / red[0]; __syncthreads();

    int d    = tid & 63;
    int half = tid >> 6;
    float acc = 0.f;
    for (int k = half; k < nk; k += 2) {
        acc += sc[k] * qkv[((long)b*TOK + k)*D3 + 2*DMODEL + h*HD + d];
    }
    red[tid] = acc; __syncthreads();
    if (half == 0)
        out[row*DMODEL + h*HD + d] = rnd_tf32((red[tid] + red[tid + 64]) * inv);
}

// ---------------- launcher ----------------
extern "C" void kernel_launch(void* const* d_in, const int* in_sizes, int n_in,
                              void* d_out, int out_size) {
    const int*   ids    = (const int*)  d_in[0];
    const float* wte    = (const float*)d_in[1];
    const float* wpe    = (const float*)d_in[2];
    const float* ln1_g  = (const float*)d_in[3];
    const float* ln1_b  = (const float*)d_in[4];
    const float* attn_w = (const float*)d_in[5];
    const float* attn_b = (const float*)d_in[6];
    const float* proj_w = (const float*)d_in[7];
    const float* proj_b = (const float*)d_in[8];
    const float* ln2_g  = (const float*)d_in[9];
    const float* ln2_b  = (const float*)d_in[10];
    const float* fc_w   = (const float*)d_in[11];
    const float* fc_b   = (const float*)d_in[12];
    const float* out_w  = (const float*)d_in[13];
    const float* out_b  = (const float*)d_in[14];
    const float* lnf_g  = (const float*)d_in[15];
    const float* lnf_b  = (const float*)d_in[16];
    float* logits = (float*)d_out;

    float *px, *ph, *pqkv, *pattn, *pmlp, *pkt;
    float *wq, *wp, *wf, *wo, *wt;
    cudaGetSymbolAddress((void**)&px,    g_x);
    cudaGetSymbolAddress((void**)&ph,    g_h);
    cudaGetSymbolAddress((void**)&pqkv,  g_qkv);
    cudaGetSymbolAddress((void**)&pattn, g_attn);
    cudaGetSymbolAddress((void**)&pmlp,  g_mlp);
    cudaGetSymbolAddress((void**)&pkt,   g_kt);
    cudaGetSymbolAddress((void**)&wq,    g_wqkv);
    cudaGetSymbolAddress((void**)&wp,    g_wproj);
    cudaGetSymbolAddress((void**)&wf,    g_wfc);
    cudaGetSymbolAddress((void**)&wo,    g_wout);
    cudaGetSymbolAddress((void**)&wt,    g_wte);

    const int SMEM_N = (STAGES*A_SZ + STAGES*(GBK*136)) * 4;   // 107,520 B
    const int SMEM_T = (STAGES*A_SZ + STAGES*(GBN*36))  * 4;   // 110,592 B
    cudaFuncSetAttribute(gemm_tc<false,0>, cudaFuncAttributeMaxDynamicSharedMemorySize, SMEM_N);
    cudaFuncSetAttribute(gemm_tc<false,1>, cudaFuncAttributeMaxDynamicSharedMemorySize, SMEM_N);
    cudaFuncSetAttribute(gemm_tc<false,2>, cudaFuncAttributeMaxDynamicSharedMemorySize, SMEM_N);
    cudaFuncSetAttribute(gemm_tc<true,0>,  cudaFuncAttributeMaxDynamicSharedMemorySize, SMEM_T);

    // pre-round all GEMM B operands to tf32 (static copies)
    round4_kernel<<<2048, 256>>>((const float4*)attn_w, (float4*)wq, NLAYER*DMODEL*D3/4);
    round4_kernel<<<2048, 256>>>((const float4*)proj_w, (float4*)wp, NLAYER*DMODEL*DMODEL/4);
    round4_kernel<<<2048, 256>>>((const float4*)fc_w,   (float4*)wf, NLAYER*DMODEL*D4/4);
    round4_kernel<<<2048, 256>>>((const float4*)out_w,  (float4*)wo, NLAYER*D4*DMODEL/4);
    round4_kernel<<<2048, 256>>>((const float4*)wte,    (float4*)wt, VOCAB*DMODEL/4);

    embed_kernel<<<(ROWS*DMODEL + 255)/256, 256>>>(ids, wte, wpe, px);

    for (int l = 0; l < NLAYER; l++) {
        // --- attention block ---
        layernorm_kernel<<<ROWS, 256>>>(px, ln1_g + l*DMODEL, ln1_b + l*DMODEL, ph);
        gemm_tc<false,0><<<dim3(ROWS/GBM, D3/GBN), 256, SMEM_N>>>(
            ph, wq + (long)l*DMODEL*D3, attn_b + l*D3, nullptr, pqkv,
            ROWS, D3, DMODEL);
        transpose_k_kernel<<<dim3(TOK/32, HD/32, BATCH*NHEAD), 256>>>(pqkv, pkt);
        attention_kernel<<<BATCH*NHEAD*TOK, 128>>>(pqkv, pkt, pattn);
        gemm_tc<false,1><<<dim3(ROWS/GBM, DMODEL/GBN), 256, SMEM_N>>>(
            pattn, wp + (long)l*DMODEL*DMODEL, proj_b + l*DMODEL, px, px,
            ROWS, DMODEL, DMODEL);
        // --- mlp block ---
        layernorm_kernel<<<ROWS, 256>>>(px, ln2_g + l*DMODEL, ln2_b + l*DMODEL, ph);
        gemm_tc<false,2><<<dim3(ROWS/GBM, D4/GBN), 256, SMEM_N>>>(
            ph, wf + (long)l*DMODEL*D4, fc_b + l*D4, nullptr, pmlp,
            ROWS, D4, DMODEL);
        gemm_tc<false,1><<<dim3(ROWS/GBM, DMODEL/GBN), 256, SMEM_N>>>(
            pmlp, wo + (long)l*D4*DMODEL, out_b + l*DMODEL, px, px,
            ROWS, DMODEL, D4);
    }

    layernorm_kernel<<<ROWS, 256>>>(px, lnf_g, lnf_b, ph);
    gemm_tc<true,0><<<dim3(ROWS/GBM, (VOCAB + GBN - 1)/GBN), 256, SMEM_T>>>(
        ph, wt, nullptr, nullptr, logits,
        ROWS, VOCAB, DMODEL);
}

// round 7
// speedup vs baseline: 4.7043x; 1.0003x over previous
#include <cuda_runtime.h>
#include <cuda_bf16.h>
#include <math.h>
#include <stdint.h>

// ---------------- problem constants ----------------
#define BATCH 2
#define TOK   1024
#define ROWS  (BATCH*TOK)   // 2048
#define DMODEL 768
#define NHEAD 12
#define HD    64
#define NLAYER 4
#define VOCAB 50257
#define D3    (3*DMODEL)    // 2304
#define D4    (4*DMODEL)    // 3072

// ---------------- scratch (static device allocations) ----------------
__device__ float g_x   [ROWS*DMODEL];
__device__ float g_h   [ROWS*DMODEL];
__device__ float g_qkv [ROWS*D3];
__device__ float g_attn[ROWS*DMODEL];
__device__ float g_mlp [ROWS*D4];
__device__ float g_kt  [BATCH*NHEAD*HD*TOK];   // K transposed: [b,h,d,t]

// pre-rounded tf32 weight copies
__device__ float g_wqkv[NLAYER*DMODEL*D3];
__device__ float g_wproj[NLAYER*DMODEL*DMODEL];
__device__ float g_wfc [NLAYER*DMODEL*D4];
__device__ float g_wout[NLAYER*D4*DMODEL];
__device__ float g_wte [VOCAB*DMODEL];

__device__ __forceinline__ float rnd_tf32(float x) {
    uint32_t u; asm("cvt.rna.tf32.f32 %0, %1;" : "=r"(u) : "f"(x));
    return __uint_as_float(u);
}

// ---------------- tf32 pre-rounding copy ----------------
__global__ void round4_kernel(const float4* __restrict__ in,
                              float4* __restrict__ out, int n4) {
    for (int i = blockIdx.x*blockDim.x + threadIdx.x; i < n4;
         i += gridDim.x*blockDim.x) {
        float4 v = in[i];
        v.x = rnd_tf32(v.x); v.y = rnd_tf32(v.y);
        v.z = rnd_tf32(v.z); v.w = rnd_tf32(v.w);
        out[i] = v;
    }
}

// ---------------- embedding ----------------
__global__ void embed_kernel(const int* __restrict__ ids,
                             const float* __restrict__ wte,
                             const float* __restrict__ wpe,
                             float* __restrict__ x) {
    int idx = blockIdx.x * blockDim.x + threadIdx.x;
    if (idx >= ROWS*DMODEL) return;
    int row = idx / DMODEL;
    int d   = idx - row*DMODEL;
    int t   = row % TOK;
    x[idx] = wte[(long)ids[row]*DMODEL + d] + wpe[t*DMODEL + d];
}

// ---------------- layernorm (one block per row), tf32-rounded output ----------------
__global__ void layernorm_kernel(const float* __restrict__ x,
                                 const float* __restrict__ g,
                                 const float* __restrict__ b,
                                 float* __restrict__ out) {
    __shared__ float row[DMODEL];
    __shared__ float red[256];
    int r = blockIdx.x;
    int tid = threadIdx.x;
    const float* xr = x + (long)r*DMODEL;

    float s = 0.f;
    for (int i = tid; i < DMODEL; i += 256) { float v = xr[i]; row[i] = v; s += v; }
    red[tid] = s; __syncthreads();
    for (int off = 128; off > 0; off >>= 1) { if (tid < off) red[tid] += red[tid+off]; __syncthreads(); }
    float mean = red[0] * (1.f/DMODEL);
    __syncthreads();

    float vs = 0.f;
    for (int i = tid; i < DMODEL; i += 256) { float d = row[i] - mean; vs += d*d; }
    red[tid] = vs; __syncthreads();
    for (int off = 128; off > 0; off >>= 1) { if (tid < off) red[tid] += red[tid+off]; __syncthreads(); }
    float inv = rsqrtf(red[0] * (1.f/DMODEL) + 1e-5f);

    float* orow = out + (long)r*DMODEL;
    for (int i = tid; i < DMODEL; i += 256)
        orow[i] = rnd_tf32(g[i] * (row[i] - mean) * inv + b[i]);
}

// ---------------- TF32 tensor-core GEMM, cp.async 3-stage ----------------
// Inputs A and B must already be tf32-rounded. fp32 accumulate.
// TRANSB=false: B row-major [K,N] (N mult of 128). TRANSB=true: B [N,K].
// EPI: 0 = bias only, 1 = bias + residual add, 2 = bias + exact GELU (tf32-rounded out)
// Block 128x128x32, 256 threads, 8 warps as 2(M) x 4(N), warp tile 64x32.
// Grid: x = M blocks, y = N blocks (M-major rasterization for B reuse).

__device__ __forceinline__ void mma_tf32(float* c, const uint32_t* a,
                                         uint32_t b0, uint32_t b1) {
    asm volatile(
        "mma.sync.aligned.m16n8k8.row.col.f32.tf32.tf32.f32 "
        "{%0,%1,%2,%3}, {%4,%5,%6,%7}, {%8,%9}, {%0,%1,%2,%3};"
        : "+f"(c[0]), "+f"(c[1]), "+f"(c[2]), "+f"(c[3])
        : "r"(a[0]), "r"(a[1]), "r"(a[2]), "r"(a[3]), "r"(b0), "r"(b1));
}

__device__ __forceinline__ void cp_async16(float* smem_ptr, const float* gptr) {
    uint32_t saddr = (uint32_t)__cvta_generic_to_shared(smem_ptr);
    asm volatile("cp.async.cg.shared.global [%0], [%1], 16;\n" :: "r"(saddr), "l"(gptr));
}
__device__ __forceinline__ void cp_commit() { asm volatile("cp.async.commit_group;\n"); }
template<int N> __device__ __forceinline__ void cp_wait() {
    asm volatile("cp.async.wait_group %0;\n" :: "n"(N));
}

#define GBM 128
#define GBN 128
#define GBK 32
#define STAGES 3
#define ASTR 36
#define A_SZ (GBM*ASTR)               // 4608 floats / stage

template<bool TRANSB, int EPI>
__global__ void __launch_bounds__(256, 2)
gemm_tc(const float* __restrict__ A,
        const float* __restrict__ B,
        const float* __restrict__ bias,
        const float* __restrict__ resid,
        float* __restrict__ C,
        int M, int N, int K) {
    constexpr int BSTR = TRANSB ? 36 : 136;               // floats
    constexpr int B_SZ = TRANSB ? (GBN*36) : (GBK*136);   // 4608 : 4352

    extern __shared__ float smem[];
    float* As = smem;                     // STAGES * A_SZ
    float* Bs = smem + STAGES*A_SZ;       // STAGES * B_SZ

    const int tid  = threadIdx.x;
    const int lane = tid & 31;
    const int warp = tid >> 5;
    const int wm   = warp >> 2;     // 0..1  (64-row M slab)
    const int wn   = warp & 3;      // 0..3  (32-col N slab)
    const int bm   = blockIdx.x * GBM;    // M-major rasterization
    const int bn   = blockIdx.y * GBN;

    float acc[4][4][4];
    #pragma unroll
    for (int i = 0; i < 4; i++)
        #pragma unroll
        for (int j = 0; j < 4; j++)
            #pragma unroll
            for (int k = 0; k < 4; k++) acc[i][j][k] = 0.f;

    auto issue_load = [&](int stage, int k0) {
        float* a = As + stage*A_SZ;
        #pragma unroll
        for (int p = 0; p < 4; p++) {
            int r = (tid >> 3) + p*32;
            int c = (tid & 7) * 4;
            cp_async16(a + r*ASTR + c, A + (long)(bm + r)*K + k0 + c);
        }
        float* bsh = Bs + stage*B_SZ;
        if (!TRANSB) {
            int kk = tid >> 3;
            #pragma unroll
            for (int p = 0; p < 4; p++) {
                int c = ((tid & 7) + p*8) * 4;
                cp_async16(bsh + kk*BSTR + c, B + (long)(k0 + kk)*N + bn + c);
            }
        } else {
            #pragma unroll
            for (int p = 0; p < 4; p++) {
                int nn = (tid >> 3) + p*32;
                int n  = bn + nn; if (n > N-1) n = N-1;
                int c  = (tid & 7) * 4;
                cp_async16(bsh + nn*BSTR + c, B + (long)n*K + k0 + c);
            }
        }
    };

    auto compute = [&](int stage) {
        const float* a   = As + stage*A_SZ;
        const float* bsh = Bs + stage*B_SZ;
        #pragma unroll
        for (int ks = 0; ks < 4; ks++) {
            const int k = ks*8;
            uint32_t af[4][4];
            #pragma unroll
            for (int mt = 0; mt < 4; mt++) {
                int m  = wm*64 + mt*16 + (lane >> 2);
                int kc = k + (lane & 3);
                af[mt][0] = __float_as_uint(a[m*ASTR + kc]);
                af[mt][1] = __float_as_uint(a[(m + 8)*ASTR + kc]);
                af[mt][2] = __float_as_uint(a[m*ASTR + kc + 4]);
                af[mt][3] = __float_as_uint(a[(m + 8)*ASTR + kc + 4]);
            }
            uint32_t bf[4][2];
            #pragma unroll
            for (int nt = 0; nt < 4; nt++) {
                int n = wn*32 + nt*8 + (lane >> 2);
                if (!TRANSB) {
                    bf[nt][0] = __float_as_uint(bsh[(k +     (lane & 3))*BSTR + n]);
                    bf[nt][1] = __float_as_uint(bsh[(k + 4 + (lane & 3))*BSTR + n]);
                } else {
                    bf[nt][0] = __float_as_uint(bsh[n*BSTR + k +     (lane & 3)]);
                    bf[nt][1] = __float_as_uint(bsh[n*BSTR + k + 4 + (lane & 3)]);
                }
            }
            #pragma unroll
            for (int mt = 0; mt < 4; mt++)
                #pragma unroll
                for (int nt = 0; nt < 4; nt++)
                    mma_tf32(acc[mt][nt], af[mt], bf[nt][0], bf[nt][1]);
        }
    };

    const int NIT = K / GBK;
    #pragma unroll
    for (int s = 0; s < STAGES-1; s++) { issue_load(s, s*GBK); cp_commit(); }

    for (int it = 0; it < NIT; ++it) {
        cp_wait<STAGES-2>();
        __syncthreads();
        int nxt = it + STAGES - 1;
        if (nxt < NIT) issue_load(nxt % STAGES, nxt*GBK);
        cp_commit();
        compute(it % STAGES);
    }

    // epilogue
    #pragma unroll
    for (int mt = 0; mt < 4; mt++) {
        #pragma unroll
        for (int nt = 0; nt < 4; nt++) {
            int row0 = bm + wm*64 + mt*16 + (lane >> 2);
            int col0 = bn + wn*32 + nt*8 + (lane & 3)*2;
            #pragma unroll
            for (int h = 0; h < 2; h++) {
                int m = row0 + h*8;
                #pragma unroll
                for (int j = 0; j < 2; j++) {
                    int n = col0 + j;
                    if (n < N) {
                        float v = acc[mt][nt][h*2 + j];
                        if (bias) v += bias[n];
                        if (EPI == 1) v += resid[(long)m*N + n];
                        if (EPI == 2) v = rnd_tf32(0.5f * v * (1.f + erff(v * 0.70710678118654752f)));
                        C[(long)m*N + n] = v;
                    }
                }
            }
        }
    }
}

// ---------------- K transpose: qkv K-section -> Kt[b,h,d,t] ----------------
__global__ void transpose_k_kernel(const float* __restrict__ qkv,
                                   float* __restrict__ kt) {
    __shared__ float tile[32][33];
    int bh = blockIdx.z;                 // b*NHEAD + h
    int b  = bh / NHEAD, h = bh % NHEAD;
    int t0 = blockIdx.x * 32, d0 = blockIdx.y * 32;
    int tx = threadIdx.x & 31, ty = threadIdx.x >> 5;    // 256 thr: ty 0..7

    #pragma unroll
    for (int i = ty; i < 32; i += 8)
        tile[i][tx] = qkv[((long)(b*TOK + t0 + i))*D3 + DMODEL + h*HD + d0 + tx];
    __syncthreads();
    #pragma unroll
    for (int i = ty; i < 32; i += 8)
        kt[((long)(bh*HD + d0 + i))*TOK + t0 + tx] = tile[tx][i];
}

// ---------------- attention: one block per (b, h, q-row) ----------------
__global__ void attention_kernel(const float* __restrict__ qkv,
                                 const float* __restrict__ kt,
                                 float* __restrict__ out) {
    __shared__ float sc[TOK];
    __shared__ float qs[HD];
    __shared__ float red[128];

    int bid = blockIdx.x;
    int q_row = bid & (TOK-1);
    int h     = (bid >> 10) % NHEAD;
    int b     = bid / (TOK*NHEAD);
    int tid   = threadIdx.x;   // 128 threads

    long row = (long)b*TOK + q_row;
    const float* qptr = qkv + row*D3 + h*HD;
    if (tid < HD) qs[tid] = qptr[tid];
    __syncthreads();

    int nk = q_row + 1;
    const float scale = 0.125f;   // 1/sqrt(64)
    const float* kbase = kt + (long)(b*NHEAD + h)*HD*TOK;

    for (int k = tid; k < nk; k += 128) {
        float s = 0.f;
        #pragma unroll
        for (int d = 0; d < HD; d++) s += qs[d] * kbase[d*TOK + k];
        sc[k] = s * scale;
    }
    __syncthreads();

    float m = -INFINITY;
    for (int k = tid; k < nk; k += 128) m = fmaxf(m, sc[k]);
    red[tid] = m; __syncthreads();
    for (int off = 64; off > 0; off >>= 1) { if (tid < off) red[tid] = fmaxf(red[tid], red[tid+off]); __syncthreads(); }
    float mx = red[0]; __syncthreads();

    float s = 0.f;
    for (int k = tid; k < nk; k += 128) { float e = expf(sc[k] - mx); sc[k] = e; s += e; }
    red[tid] = s; __syncthreads();
    for (int off = 64; off > 0; off >>= 1) { if (tid < off) red[tid] += red[tid+off]; __syncthreads(); }
    float inv = 1.f / red[0]; __syncthreads();

    int d    = tid & 63;
    int half = tid >> 6;
    float acc = 0.f;
    for (int k = half; k < nk; k += 2) {
        acc += sc[k] * qkv[((long)b*TOK + k)*D3 + 2*DMODEL + h*HD + d];
    }
    red[tid] = acc; __syncthreads();
    if (half == 0)
        out[row*DMODEL + h*HD + d] = rnd_tf32((red[tid] + red[tid + 64]) * inv);
}

// ---------------- launcher ----------------
extern "C" void kernel_launch(void* const* d_in, const int* in_sizes, int n_in,
                              void* d_out, int out_size) {
    const int*   ids    = (const int*)  d_in[0];
    const float* wte    = (const float*)d_in[1];
    const float* wpe    = (const float*)d_in[2];
    const float* ln1_g  = (const float*)d_in[3];
    const float* ln1_b  = (const float*)d_in[4];
    const float* attn_w = (const float*)d_in[5];
    const float* attn_b = (const float*)d_in[6];
    const float* proj_w = (const float*)d_in[7];
    const float* proj_b = (const float*)d_in[8];
    const float* ln2_g  = (const float*)d_in[9];
    const float* ln2_b  = (const float*)d_in[10];
    const float* fc_w   = (const float*)d_in[11];
    const float* fc_b   = (const float*)d_in[12];
    const float* out_w  = (const float*)d_in[13];
    const float* out_b  = (const float*)d_in[14];
    const float* lnf_g  = (const float*)d_in[15];
    const float* lnf_b  = (const float*)d_in[16];
    float* logits = (float*)d_out;

    float *px, *ph, *pqkv, *pattn, *pmlp, *pkt;
    float *wq, *wp, *wf, *wo, *wt;
    cudaGetSymbolAddress((void**)&px,    g_x);
    cudaGetSymbolAddress((void**)&ph,    g_h);
    cudaGetSymbolAddress((void**)&pqkv,  g_qkv);
    cudaGetSymbolAddress((void**)&pattn, g_attn);
    cudaGetSymbolAddress((void**)&pmlp,  g_mlp);
    cudaGetSymbolAddress((void**)&pkt,   g_kt);
    cudaGetSymbolAddress((void**)&wq,    g_wqkv);
    cudaGetSymbolAddress((void**)&wp,    g_wproj);
    cudaGetSymbolAddress((void**)&wf,    g_wfc);
    cudaGetSymbolAddress((void**)&wo,    g_wout);
    cudaGetSymbolAddress((void**)&wt,    g_wte);

    const int SMEM_N = (STAGES*A_SZ + STAGES*(GBK*136)) * 4;   // 107,520 B
    const int SMEM_T = (STAGES*A_SZ + STAGES*(GBN*36))  * 4;   // 110,592 B
    cudaFuncSetAttribute(gemm_tc<false,0>, cudaFuncAttributeMaxDynamicSharedMemorySize, SMEM_N);
    cudaFuncSetAttribute(gemm_tc<false,1>, cudaFuncAttributeMaxDynamicSharedMemorySize, SMEM_N);
    cudaFuncSetAttribute(gemm_tc<false,2>, cudaFuncAttributeMaxDynamicSharedMemorySize, SMEM_N);
    cudaFuncSetAttribute(gemm_tc<true,0>,  cudaFuncAttributeMaxDynamicSharedMemorySize, SMEM_T);

    // pre-round all GEMM B operands to tf32 (static copies)
    round4_kernel<<<2048, 256>>>((const float4*)attn_w, (float4*)wq, NLAYER*DMODEL*D3/4);
    round4_kernel<<<2048, 256>>>((const float4*)proj_w, (float4*)wp, NLAYER*DMODEL*DMODEL/4);
    round4_kernel<<<2048, 256>>>((const float4*)fc_w,   (float4*)wf, NLAYER*DMODEL*D4/4);
    round4_kernel<<<2048, 256>>>((const float4*)out_w,  (float4*)wo, NLAYER*D4*DMODEL/4);
    round4_kernel<<<2048, 256>>>((const float4*)wte,    (float4*)wt, VOCAB*DMODEL/4);

    embed_kernel<<<(ROWS*DMODEL + 255)/256, 256>>>(ids, wte, wpe, px);

    for (int l = 0; l < NLAYER; l++) {
        // --- attention block ---
        layernorm_kernel<<<ROWS, 256>>>(px, ln1_g + l*DMODEL, ln1_b + l*DMODEL, ph);
        gemm_tc<false,0><<<dim3(ROWS/GBM, D3/GBN), 256, SMEM_N>>>(
            ph, wq + (long)l*DMODEL*D3, attn_b + l*D3, nullptr, pqkv,
            ROWS, D3, DMODEL);
        transpose_k_kernel<<<dim3(TOK/32, HD/32, BATCH*NHEAD), 256>>>(pqkv, pkt);
        attention_kernel<<<BATCH*NHEAD*TOK, 128>>>(pqkv, pkt, pattn);
        gemm_tc<false,1><<<dim3(ROWS/GBM, DMODEL/GBN), 256, SMEM_N>>>(
            pattn, wp + (long)l*DMODEL*DMODEL, proj_b + l*DMODEL, px, px,
            ROWS, DMODEL, DMODEL);
        // --- mlp block ---
        layernorm_kernel<<<ROWS, 256>>>(px, ln2_g + l*DMODEL, ln2_b + l*DMODEL, ph);
        gemm_tc<false,2><<<dim3(ROWS/GBM, D4/GBN), 256, SMEM_N>>>(
            ph, wf + (long)l*DMODEL*D4, fc_b + l*D4, nullptr, pmlp,
            ROWS, D4, DMODEL);
        gemm_tc<false,1><<<dim3(ROWS/GBM, DMODEL/GBN), 256, SMEM_N>>>(
            pmlp, wo + (long)l*D4*DMODEL, out_b + l*DMODEL, px, px,
            ROWS, DMODEL, D4);
    }

    layernorm_kernel<<<ROWS, 256>>>(px, lnf_g, lnf_b, ph);
    gemm_tc<true,0><<<dim3(ROWS/GBM, (VOCAB + GBN - 1)/GBN), 256, SMEM_T>>>(
        ph, wt, nullptr, nullptr, logits,
        ROWS, VOCAB, DMODEL);
}

// round 12
// speedup vs baseline: 5.4609x; 1.1608x over previous
#include <cuda_runtime.h>
#include <cuda_fp16.h>
#include <math.h>
#include <stdint.h>

#define BATCH 2
#define TOK   1024
#define ROWS  (BATCH*TOK)
#define DMODEL 768
#define NHEAD 12
#define HD    64
#define NLAYER 4
#define VOCAB 50257
#define VPAD  50432          // 394*128
#define D3    (3*DMODEL)
#define D4    (4*DMODEL)

// ---------------- scratch ----------------
__device__ __align__(128) float g_x  [ROWS*DMODEL];
__device__ __align__(128) float g_qkv[ROWS*D3];
__device__ __align__(128) float g_kt [BATCH*NHEAD*HD*TOK];

__device__ __align__(128) __half g_h   [ROWS*DMODEL];   // LN out (GEMM A)
__device__ __align__(128) __half g_attn[ROWS*DMODEL];   // attention out
__device__ __align__(128) __half g_mlp [ROWS*D4];       // GELU out

// fp16 weights, [N][K] layout
__device__ __align__(128) __half g_wq[NLAYER*D3*DMODEL];
__device__ __align__(128) __half g_wp[NLAYER*DMODEL*DMODEL];
__device__ __align__(128) __half g_wf[NLAYER*D4*DMODEL];
__device__ __align__(128) __half g_wo[NLAYER*DMODEL*D4];
__device__ __align__(128) __half g_wt[(long)VPAD*DMODEL];

// ---------------- helpers ----------------
__device__ __forceinline__ void cp16h(const __half* s, const __half* g) {
    uint32_t sa = (uint32_t)__cvta_generic_to_shared(s);
    asm volatile("cp.async.cg.shared.global [%0], [%1], 16;\n" :: "r"(sa), "l"(g));
}
__device__ __forceinline__ void cp_commit() { asm volatile("cp.async.commit_group;\n"); }
template<int N> __device__ __forceinline__ void cp_wait() {
    asm volatile("cp.async.wait_group %0;\n" :: "n"(N));
}
__device__ __forceinline__ void mma_fp16(float* c, const uint32_t* a, uint32_t b0, uint32_t b1) {
    asm volatile(
        "mma.sync.aligned.m16n8k16.row.col.f32.f16.f16.f32 "
        "{%0,%1,%2,%3}, {%4,%5,%6,%7}, {%8,%9}, {%0,%1,%2,%3};"
        : "+f"(c[0]), "+f"(c[1]), "+f"(c[2]), "+f"(c[3])
        : "r"(a[0]), "r"(a[1]), "r"(a[2]), "r"(a[3]), "r"(b0), "r"(b1));
}

// ---------------- weight prep: w[K][N] fp32 -> fp16 [N][K] ----------------
__global__ void prep_wt(const float* __restrict__ w, __half* __restrict__ o, int K, int N) {
    __shared__ float t[32][33];
    int l = blockIdx.z;
    w += (long)l*K*N;  o += (long)l*N*K;
    int n0 = blockIdx.x*32, k0 = blockIdx.y*32;
    int tx = threadIdx.x & 31, ty = threadIdx.x >> 5;
    #pragma unroll
    for (int i = ty; i < 32; i += 8) t[i][tx] = w[(long)(k0+i)*N + n0 + tx];
    __syncthreads();
    #pragma unroll
    for (int i = ty; i < 32; i += 8)
        o[(long)(n0+i)*K + k0 + tx] = __float2half_rn(t[tx][i]);
}

// wte [V][D] fp32 -> fp16 padded to VPAD rows (already [N][K])
__global__ void prep_wte(const float* __restrict__ w, __half* __restrict__ o) {
    long n = (long)VPAD*DMODEL;
    for (long i = blockIdx.x*(long)blockDim.x + threadIdx.x; i < n;
         i += (long)gridDim.x*blockDim.x) {
        long row = i / DMODEL;
        o[i] = __float2half_rn(row < VOCAB ? w[i] : 0.f);
    }
}

// ---------------- embedding ----------------
__global__ void embed_kernel(const int* __restrict__ ids, const float* __restrict__ wte,
                             const float* __restrict__ wpe, float* __restrict__ x) {
    int idx = blockIdx.x * blockDim.x + threadIdx.x;
    if (idx >= ROWS*DMODEL) return;
    int row = idx / DMODEL, d = idx - row*DMODEL, t = row % TOK;
    x[idx] = wte[(long)ids[row]*DMODEL + d] + wpe[t*DMODEL + d];
}

// ---------------- layernorm -> fp16 ----------------
__global__ void layernorm_kernel(const float* __restrict__ x, const float* __restrict__ g,
                                 const float* __restrict__ b, __half* __restrict__ out) {
    __shared__ float row[DMODEL];
    __shared__ float red[256];
    int r = blockIdx.x, tid = threadIdx.x;
    const float* xr = x + (long)r*DMODEL;

    float s = 0.f;
    for (int i = tid; i < DMODEL; i += 256) { float v = xr[i]; row[i] = v; s += v; }
    red[tid] = s; __syncthreads();
    for (int o = 128; o > 0; o >>= 1) { if (tid < o) red[tid] += red[tid+o]; __syncthreads(); }
    float mean = red[0] * (1.f/DMODEL);
    __syncthreads();
    float vs = 0.f;
    for (int i = tid; i < DMODEL; i += 256) { float d = row[i] - mean; vs += d*d; }
    red[tid] = vs; __syncthreads();
    for (int o = 128; o > 0; o >>= 1) { if (tid < o) red[tid] += red[tid+o]; __syncthreads(); }
    float inv = rsqrtf(red[0] * (1.f/DMODEL) + 1e-5f);

    __half* orow = out + (long)r*DMODEL;
    for (int i = tid; i < DMODEL; i += 256)
        orow[i] = __float2half_rn(g[i] * (row[i] - mean) * inv + b[i]);
}

// ---------------- fp16 HMMA GEMM: C[M,N] = A[M,K] @ B[N,K]^T ----------------
// EPI: 0 = bias -> C fp32 ; 1 = bias+resid -> C fp32 ; 2 = bias+GELU -> Ch fp16 ;
//      3 = no bias -> C fp32, cols masked n < Nn
// Block 128x128x32, 256 thr, 8 warps 2(M)x4(N), warp tile 64x32, 3-stage cp.async.
#define ASTR   56                  // halves per smem row (112B, 16B-mult, conflict-free frags)
#define TILE_H (128*ASTR)          // 7168 halves per tile
#define STG_H  (2*TILE_H)          // A+B per stage
#define STAGES 3

template<int EPI>
__global__ void __launch_bounds__(256, 2)
gemm_hmma(const __half* __restrict__ A, const __half* __restrict__ B,
          const float* __restrict__ bias, const float* __restrict__ resid,
          float* __restrict__ C, __half* __restrict__ Ch,
          int Nn, int K) {
    extern __shared__ __half sh[];
    const int tid = threadIdx.x, lane = tid & 31, warp = tid >> 5;
    const int wm = warp >> 2, wn = warp & 3;
    const long bm = (long)blockIdx.x * 128;   // M-major rasterization
    const long bn = (long)blockIdx.y * 128;

    float acc[4][4][4];
    #pragma unroll
    for (int i = 0; i < 4; i++)
        #pragma unroll
        for (int j = 0; j < 4; j++)
            #pragma unroll
            for (int k = 0; k < 4; k++) acc[i][j][k] = 0.f;

    auto issue_load = [&](int s, int k0) {
        const __half* ab = A + bm*K + k0;
        const __half* bb = B + bn*K + k0;
        __half* sa = sh + s*STG_H;
        __half* sbm = sa + TILE_H;
        #pragma unroll
        for (int i = 0; i < 2; i++) {
            int ch = i*256 + tid;
            int r = ch >> 2, c8 = (ch & 3) * 8;
            cp16h(sa + r*ASTR + c8, ab + (long)r*K + c8);
        }
        #pragma unroll
        for (int i = 0; i < 2; i++) {
            int ch = i*256 + tid;
            int r = ch >> 2, c8 = (ch & 3) * 8;
            cp16h(sbm + r*ASTR + c8, bb + (long)r*K + c8);
        }
        cp_commit();
    };

    auto compute = [&](int s) {
        const __half* a = sh + s*STG_H;
        const __half* b = a + TILE_H;
        #pragma unroll
        for (int ks = 0; ks < 2; ks++) {
            const int k = ks*16 + (lane & 3)*2;
            uint32_t af[4][4];
            #pragma unroll
            for (int mt = 0; mt < 4; mt++) {
                int m = wm*64 + mt*16 + (lane >> 2);
                af[mt][0] = *(const uint32_t*)(a + m*ASTR + k);
                af[mt][1] = *(const uint32_t*)(a + (m+8)*ASTR + k);
                af[mt][2] = *(const uint32_t*)(a + m*ASTR + k + 8);
                af[mt][3] = *(const uint32_t*)(a + (m+8)*ASTR + k + 8);
            }
            uint32_t bf[4][2];
            #pragma unroll
            for (int nt = 0; nt < 4; nt++) {
                int n = wn*32 + nt*8 + (lane >> 2);
                bf[nt][0] = *(const uint32_t*)(b + n*ASTR + k);
                bf[nt][1] = *(const uint32_t*)(b + n*ASTR + k + 8);
            }
            #pragma unroll
            for (int mt = 0; mt < 4; mt++)
                #pragma unroll
                for (int nt = 0; nt < 4; nt++)
                    mma_fp16(acc[mt][nt], af[mt], bf[nt][0], bf[nt][1]);
        }
    };

    const int NIT = K / 32;
    #pragma unroll
    for (int s = 0; s < STAGES-1; s++) issue_load(s, s*32);

    for (int it = 0; it < NIT; ++it) {
        cp_wait<STAGES-2>();
        __syncthreads();
        int nxt = it + STAGES - 1;
        if (nxt < NIT) issue_load(nxt % STAGES, nxt*32);
        else cp_commit();
        compute(it % STAGES);
    }

    // ---------------- epilogue ----------------
    #pragma unroll
    for (int mt = 0; mt < 4; mt++) {
        #pragma unroll
        for (int nt = 0; nt < 4; nt++) {
            long row0 = bm + wm*64 + mt*16 + (lane >> 2);
            long col0 = bn + wn*32 + nt*8 + (lane & 3)*2;
            #pragma unroll
            for (int h = 0; h < 2; h++) {
                long m = row0 + h*8;
                #pragma unroll
                for (int j = 0; j < 2; j++) {
                    long n = col0 + j;
                    float v = acc[mt][nt][h*2 + j];
                    if (EPI != 3) v += bias[n];
                    if (EPI == 1) v += resid[m*Nn + n];
                    if (EPI == 2) {
                        float gv = 0.5f * v * (1.f + erff(v * 0.70710678118654752f));
                        Ch[m*Nn + n] = __float2half_rn(gv);
                    } else if (EPI == 3) {
                        if (n < Nn) C[m*Nn + n] = v;
                    } else {
                        C[m*Nn + n] = v;
                    }
                }
            }
        }
    }
}

// ---------------- K transpose ----------------
__global__ void transpose_k_kernel(const float* __restrict__ qkv, float* __restrict__ kt) {
    __shared__ float tile[32][33];
    int bh = blockIdx.z, b = bh / NHEAD, h = bh % NHEAD;
    int t0 = blockIdx.x * 32, d0 = blockIdx.y * 32;
    int tx = threadIdx.x & 31, ty = threadIdx.x >> 5;
    #pragma unroll
    for (int i = ty; i < 32; i += 8)
        tile[i][tx] = qkv[((long)(b*TOK + t0 + i))*D3 + DMODEL + h*HD + d0 + tx];
    __syncthreads();
    #pragma unroll
    for (int i = ty; i < 32; i += 8)
        kt[((long)(bh*HD + d0 + i))*TOK + t0 + tx] = tile[tx][i];
}

// ---------------- attention (per (b,h,q) block) -> fp16 ----------------
__global__ void attention_kernel(const float* __restrict__ qkv, const float* __restrict__ kt,
                                 __half* __restrict__ out) {
    __shared__ float sc[TOK];
    __shared__ float qs[HD];
    __shared__ float red[128];

    int bid = blockIdx.x;
    int q_row = bid & (TOK-1);
    int h = (bid >> 10) % NHEAD;
    int b = bid / (TOK*NHEAD);
    int tid = threadIdx.x;

    long row = (long)b*TOK + q_row;
    if (tid < HD) qs[tid] = qkv[row*D3 + h*HD + tid];
    __syncthreads();

    int nk = q_row + 1;
    const float* kbase = kt + (long)(b*NHEAD + h)*HD*TOK;
    for (int k = tid; k < nk; k += 128) {
        float s = 0.f;
        #pragma unroll
        for (int d = 0; d < HD; d++) s += qs[d] * kbase[d*TOK + k];
        sc[k] = s * 0.125f;
    }
    __syncthreads();

    float m = -INFINITY;
    for (int k = tid; k < nk; k += 128) m = fmaxf(m, sc[k]);
    red[tid] = m; __syncthreads();
    for (int o = 64; o > 0; o >>= 1) { if (tid < o) red[tid] = fmaxf(red[tid], red[tid+o]); __syncthreads(); }
    float mx = red[0]; __syncthreads();

    float s = 0.f;
    for (int k = tid; k < nk; k += 128) { float e = expf(sc[k] - mx); sc[k] = e; s += e; }
    red[tid] = s; __syncthreads();
    for (int o = 64; o > 0; o >>= 1) { if (tid < o) red[tid] += red[tid+o]; __syncthreads(); }
    float inv = 1.f / red[0]; __syncthreads();

    int d = tid & 63, half = tid >> 6;
    float acc = 0.f;
    for (int k = half; k < nk; k += 2)
        acc += sc[k] * qkv[((long)b*TOK + k)*D3 + 2*DMODEL + h*HD + d];
    red[tid] = acc; __syncthreads();
    if (half == 0)
        out[row*DMODEL + h*HD + d] = __float2half_rn((red[tid] + red[tid + 64]) * inv);
}

// ---------------- launcher ----------------
#define SYM(p, s) cudaGetSymbolAddress((void**)&p, s)

extern "C" void kernel_launch(void* const* d_in, const int* in_sizes, int n_in,
                              void* d_out, int out_size) {
    const int*   ids    = (const int*)  d_in[0];
    const float* wte    = (const float*)d_in[1];
    const float* wpe    = (const float*)d_in[2];
    const float* ln1_g  = (const float*)d_in[3];
    const float* ln1_b  = (const float*)d_in[4];
    const float* attn_w = (const float*)d_in[5];
    const float* attn_b = (const float*)d_in[6];
    const float* proj_w = (const float*)d_in[7];
    const float* proj_b = (const float*)d_in[8];
    const float* ln2_g  = (const float*)d_in[9];
    const float* ln2_b  = (const float*)d_in[10];
    const float* fc_w   = (const float*)d_in[11];
    const float* fc_b   = (const float*)d_in[12];
    const float* out_w  = (const float*)d_in[13];
    const float* out_b  = (const float*)d_in[14];
    const float* lnf_g  = (const float*)d_in[15];
    const float* lnf_b  = (const float*)d_in[16];
    float* logits = (float*)d_out;

    float *px, *pqkv, *pkt;
    __half *ph, *pat, *pml, *wq, *wp, *wf, *wo, *wt;
    SYM(px, g_x); SYM(pqkv, g_qkv); SYM(pkt, g_kt);
    SYM(ph, g_h); SYM(pat, g_attn); SYM(pml, g_mlp);
    SYM(wq, g_wq); SYM(wp, g_wp); SYM(wf, g_wf); SYM(wo, g_wo); SYM(wt, g_wt);

    const int SMEM = STAGES * STG_H * 2;   // 86,016 B
    cudaFuncSetAttribute(gemm_hmma<0>, cudaFuncAttributeMaxDynamicSharedMemorySize, SMEM);
    cudaFuncSetAttribute(gemm_hmma<1>, cudaFuncAttributeMaxDynamicSharedMemorySize, SMEM);
    cudaFuncSetAttribute(gemm_hmma<2>, cudaFuncAttributeMaxDynamicSharedMemorySize, SMEM);
    cudaFuncSetAttribute(gemm_hmma<3>, cudaFuncAttributeMaxDynamicSharedMemorySize, SMEM);

    // weight prep: fp16, [N][K]
    prep_wt<<<dim3(D3/32, DMODEL/32, NLAYER), 256>>>(attn_w, wq, DMODEL, D3);
    prep_wt<<<dim3(DMODEL/32, DMODEL/32, NLAYER), 256>>>(proj_w, wp, DMODEL, DMODEL);
    prep_wt<<<dim3(D4/32, DMODEL/32, NLAYER), 256>>>(fc_w, wf, DMODEL, D4);
    prep_wt<<<dim3(DMODEL/32, D4/32, NLAYER), 256>>>(out_w, wo, D4, DMODEL);
    prep_wte<<<2048, 256>>>(wte, wt);

    embed_kernel<<<(ROWS*DMODEL + 255)/256, 256>>>(ids, wte, wpe, px);

    for (int l = 0; l < NLAYER; l++) {
        // --- attention block ---
        layernorm_kernel<<<ROWS, 256>>>(px, ln1_g + l*DMODEL, ln1_b + l*DMODEL, ph);
        gemm_hmma<0><<<dim3(ROWS/128, D3/128), 256, SMEM>>>(
            ph, wq + (long)l*D3*DMODEL, attn_b + l*D3, nullptr,
            pqkv, nullptr, D3, DMODEL);
        transpose_k_kernel<<<dim3(TOK/32, HD/32, BATCH*NHEAD), 256>>>(pqkv, pkt);
        attention_kernel<<<BATCH*NHEAD*TOK, 128>>>(pqkv, pkt, pat);
        gemm_hmma<1><<<dim3(ROWS/128, DMODEL/128), 256, SMEM>>>(
            pat, wp + (long)l*DMODEL*DMODEL, proj_b + l*DMODEL, px,
            px, nullptr, DMODEL, DMODEL);
        // --- mlp block ---
        layernorm_kernel<<<ROWS, 256>>>(px, ln2_g + l*DMODEL, ln2_b + l*DMODEL, ph);
        gemm_hmma<2><<<dim3(ROWS/128, D4/128), 256, SMEM>>>(
            ph, wf + (long)l*D4*DMODEL, fc_b + l*D4, nullptr,
            nullptr, pml, D4, DMODEL);
        gemm_hmma<1><<<dim3(ROWS/128, DMODEL/128), 256, SMEM>>>(
            pml, wo + (long)l*DMODEL*D4, out_b + l*DMODEL, px,
            px, nullptr, DMODEL, D4);
    }

    layernorm_kernel<<<ROWS, 256>>>(px, lnf_g, lnf_b, ph);
    gemm_hmma<3><<<dim3(ROWS/128, VPAD/128), 256, SMEM>>>(
        ph, wt, nullptr, nullptr, logits, nullptr, VOCAB, DMODEL);
}

// round 13
// speedup vs baseline: 6.9536x; 1.2733x over previous
#include <cuda_runtime.h>
#include <cuda_fp16.h>
#include <math.h>
#include <stdint.h>

#define BATCH 2
#define TOK   1024
#define ROWS  (BATCH*TOK)
#define DMODEL 768
#define NHEAD 12
#define HD    64
#define NLAYER 4
#define VOCAB 50257
#define VPAD  50432          // 394*128
#define D3    (3*DMODEL)
#define D4    (4*DMODEL)

// ---------------- scratch ----------------
__device__ __align__(128) float g_x  [ROWS*DMODEL];
__device__ __align__(128) float g_qkv[ROWS*D3];

__device__ __align__(128) __half g_h   [ROWS*DMODEL];   // LN out (GEMM A)
__device__ __align__(128) __half g_attn[ROWS*DMODEL];   // attention out
__device__ __align__(128) __half g_mlp [ROWS*D4];       // GELU out

// fp16 weights, [N][K] layout
__device__ __align__(128) __half g_wq[NLAYER*D3*DMODEL];
__device__ __align__(128) __half g_wp[NLAYER*DMODEL*DMODEL];
__device__ __align__(128) __half g_wf[NLAYER*D4*DMODEL];
__device__ __align__(128) __half g_wo[NLAYER*DMODEL*D4];
__device__ __align__(128) __half g_wt[(long)VPAD*DMODEL];

// ---------------- helpers ----------------
__device__ __forceinline__ void cp16h(const __half* s, const __half* g) {
    uint32_t sa = (uint32_t)__cvta_generic_to_shared(s);
    asm volatile("cp.async.cg.shared.global [%0], [%1], 16;\n" :: "r"(sa), "l"(g));
}
__device__ __forceinline__ void cp_commit() { asm volatile("cp.async.commit_group;\n"); }
template<int N> __device__ __forceinline__ void cp_wait() {
    asm volatile("cp.async.wait_group %0;\n" :: "n"(N));
}
__device__ __forceinline__ void mma_fp16(float* c, const uint32_t* a, uint32_t b0, uint32_t b1) {
    asm volatile(
        "mma.sync.aligned.m16n8k16.row.col.f32.f16.f16.f32 "
        "{%0,%1,%2,%3}, {%4,%5,%6,%7}, {%8,%9}, {%0,%1,%2,%3};"
        : "+f"(c[0]), "+f"(c[1]), "+f"(c[2]), "+f"(c[3])
        : "r"(a[0]), "r"(a[1]), "r"(a[2]), "r"(a[3]), "r"(b0), "r"(b1));
}

// ---------------- weight prep: w[K][N] fp32 -> fp16 [N][K] ----------------
__global__ void prep_wt(const float* __restrict__ w, __half* __restrict__ o, int K, int N) {
    __shared__ float t[32][33];
    int l = blockIdx.z;
    w += (long)l*K*N;  o += (long)l*N*K;
    int n0 = blockIdx.x*32, k0 = blockIdx.y*32;
    int tx = threadIdx.x & 31, ty = threadIdx.x >> 5;
    #pragma unroll
    for (int i = ty; i < 32; i += 8) t[i][tx] = w[(long)(k0+i)*N + n0 + tx];
    __syncthreads();
    #pragma unroll
    for (int i = ty; i < 32; i += 8)
        o[(long)(n0+i)*K + k0 + tx] = __float2half_rn(t[tx][i]);
}

__global__ void prep_wte(const float* __restrict__ w, __half* __restrict__ o) {
    long n = (long)VPAD*DMODEL;
    for (long i = blockIdx.x*(long)blockDim.x + threadIdx.x; i < n;
         i += (long)gridDim.x*blockDim.x) {
        long row = i / DMODEL;
        o[i] = __float2half_rn(row < VOCAB ? w[i] : 0.f);
    }
}

// ---------------- embedding ----------------
__global__ void embed_kernel(const int* __restrict__ ids, const float* __restrict__ wte,
                             const float* __restrict__ wpe, float* __restrict__ x) {
    int idx = blockIdx.x * blockDim.x + threadIdx.x;
    if (idx >= ROWS*DMODEL) return;
    int row = idx / DMODEL, d = idx - row*DMODEL, t = row % TOK;
    x[idx] = wte[(long)ids[row]*DMODEL + d] + wpe[t*DMODEL + d];
}

// ---------------- layernorm -> fp16 ----------------
__global__ void layernorm_kernel(const float* __restrict__ x, const float* __restrict__ g,
                                 const float* __restrict__ b, __half* __restrict__ out) {
    __shared__ float row[DMODEL];
    __shared__ float red[256];
    int r = blockIdx.x, tid = threadIdx.x;
    const float* xr = x + (long)r*DMODEL;

    float s = 0.f;
    for (int i = tid; i < DMODEL; i += 256) { float v = xr[i]; row[i] = v; s += v; }
    red[tid] = s; __syncthreads();
    for (int o = 128; o > 0; o >>= 1) { if (tid < o) red[tid] += red[tid+o]; __syncthreads(); }
    float mean = red[0] * (1.f/DMODEL);
    __syncthreads();
    float vs = 0.f;
    for (int i = tid; i < DMODEL; i += 256) { float d = row[i] - mean; vs += d*d; }
    red[tid] = vs; __syncthreads();
    for (int o = 128; o > 0; o >>= 1) { if (tid < o) red[tid] += red[tid+o]; __syncthreads(); }
    float inv = rsqrtf(red[0] * (1.f/DMODEL) + 1e-5f);

    __half* orow = out + (long)r*DMODEL;
    for (int i = tid; i < DMODEL; i += 256)
        orow[i] = __float2half_rn(g[i] * (row[i] - mean) * inv + b[i]);
}

// ---------------- fp16 HMMA GEMM: C[M,N] = A[M,K] @ B[N,K]^T ----------------
#define ASTR   56
#define TILE_H (128*ASTR)
#define STG_H  (2*TILE_H)
#define STAGES 3

template<int EPI>
__global__ void __launch_bounds__(256, 2)
gemm_hmma(const __half* __restrict__ A, const __half* __restrict__ B,
          const float* __restrict__ bias, const float* __restrict__ resid,
          float* __restrict__ C, __half* __restrict__ Ch,
          int Nn, int K) {
    extern __shared__ __half sh[];
    const int tid = threadIdx.x, lane = tid & 31, warp = tid >> 5;
    const int wm = warp >> 2, wn = warp & 3;
    const long bm = (long)blockIdx.x * 128;
    const long bn = (long)blockIdx.y * 128;

    float acc[4][4][4];
    #pragma unroll
    for (int i = 0; i < 4; i++)
        #pragma unroll
        for (int j = 0; j < 4; j++)
            #pragma unroll
            for (int k = 0; k < 4; k++) acc[i][j][k] = 0.f;

    auto issue_load = [&](int s, int k0) {
        const __half* ab = A + bm*K + k0;
        const __half* bb = B + bn*K + k0;
        __half* sa = sh + s*STG_H;
        __half* sbm = sa + TILE_H;
        #pragma unroll
        for (int i = 0; i < 2; i++) {
            int ch = i*256 + tid;
            int r = ch >> 2, c8 = (ch & 3) * 8;
            cp16h(sa + r*ASTR + c8, ab + (long)r*K + c8);
        }
        #pragma unroll
        for (int i = 0; i < 2; i++) {
            int ch = i*256 + tid;
            int r = ch >> 2, c8 = (ch & 3) * 8;
            cp16h(sbm + r*ASTR + c8, bb + (long)r*K + c8);
        }
        cp_commit();
    };

    auto compute = [&](int s) {
        const __half* a = sh + s*STG_H;
        const __half* b = a + TILE_H;
        #pragma unroll
        for (int ks = 0; ks < 2; ks++) {
            const int k = ks*16 + (lane & 3)*2;
            uint32_t af[4][4];
            #pragma unroll
            for (int mt = 0; mt < 4; mt++) {
                int m = wm*64 + mt*16 + (lane >> 2);
                af[mt][0] = *(const uint32_t*)(a + m*ASTR + k);
                af[mt][1] = *(const uint32_t*)(a + (m+8)*ASTR + k);
                af[mt][2] = *(const uint32_t*)(a + m*ASTR + k + 8);
                af[mt][3] = *(const uint32_t*)(a + (m+8)*ASTR + k + 8);
            }
            uint32_t bf[4][2];
            #pragma unroll
            for (int nt = 0; nt < 4; nt++) {
                int n = wn*32 + nt*8 + (lane >> 2);
                bf[nt][0] = *(const uint32_t*)(b + n*ASTR + k);
                bf[nt][1] = *(const uint32_t*)(b + n*ASTR + k + 8);
            }
            #pragma unroll
            for (int mt = 0; mt < 4; mt++)
                #pragma unroll
                for (int nt = 0; nt < 4; nt++)
                    mma_fp16(acc[mt][nt], af[mt], bf[nt][0], bf[nt][1]);
        }
    };

    const int NIT = K / 32;
    #pragma unroll
    for (int s = 0; s < STAGES-1; s++) issue_load(s, s*32);

    for (int it = 0; it < NIT; ++it) {
        cp_wait<STAGES-2>();
        __syncthreads();
        int nxt = it + STAGES - 1;
        if (nxt < NIT) issue_load(nxt % STAGES, nxt*32);
        else cp_commit();
        compute(it % STAGES);
    }

    #pragma unroll
    for (int mt = 0; mt < 4; mt++) {
        #pragma unroll
        for (int nt = 0; nt < 4; nt++) {
            long row0 = bm + wm*64 + mt*16 + (lane >> 2);
            long col0 = bn + wn*32 + nt*8 + (lane & 3)*2;
            #pragma unroll
            for (int h = 0; h < 2; h++) {
                long m = row0 + h*8;
                #pragma unroll
                for (int j = 0; j < 2; j++) {
                    long n = col0 + j;
                    float v = acc[mt][nt][h*2 + j];
                    if (EPI != 3) v += bias[n];
                    if (EPI == 1) v += resid[m*Nn + n];
                    if (EPI == 2) {
                        float gv = 0.5f * v * (1.f + erff(v * 0.70710678118654752f));
                        Ch[m*Nn + n] = __float2half_rn(gv);
                    } else if (EPI == 3) {
                        if (n < Nn) C[m*Nn + n] = v;
                    } else {
                        C[m*Nn + n] = v;
                    }
                }
            }
        }
    }
}

// ---------------- flash attention: block = (b, h, 16 q-rows) ----------------
// 128 threads: thread t -> q = t>>3 (0..15), lane-in-q lk = t&7.
// Each thread owns 8 output dims d = lk*8..lk*8+7 for its q row (fp32 acc).
// K/V tiles of 64 keys in smem; online softmax, fp32 throughout.
#define QT 16
#define KT 64

__global__ void __launch_bounds__(128)
flash_attn_kernel(const float* __restrict__ qkv, __half* __restrict__ out) {
    __shared__ float Qs[QT][68];
    __shared__ float Ks[KT][68];
    __shared__ float Vs[KT][68];
    __shared__ float Ps[QT][68];

    const int bid = blockIdx.x;
    const int qt = bid & 63;               // TOK/QT = 64
    const int h  = (bid >> 6) % NHEAD;
    const int b  = bid / (64*NHEAD);
    const int tid = threadIdx.x;
    const int q0 = qt * QT;

    // load Q tile: 16 rows x 64 floats = 256 float4
    #pragma unroll
    for (int i = 0; i < 2; i++) {
        int idx = i*128 + tid;
        int r = idx >> 4, c = idx & 15;
        *(float4*)&Qs[r][c*4] =
            *(const float4*)(qkv + ((long)(b*TOK + q0 + r))*D3 + h*HD + c*4);
    }

    const int q  = tid >> 3;
    const int lk = tid & 7;
    float acc[8];
    #pragma unroll
    for (int d = 0; d < 8; d++) acc[d] = 0.f;
    float mrow = -INFINITY, lrow = 0.f;

    const int kend = q0 + QT;
    for (int k0 = 0; k0 < kend; k0 += KT) {
        __syncthreads();                    // previous tile fully consumed
        // load K,V tiles: 64 rows x 16 float4 each
        #pragma unroll
        for (int i = 0; i < 8; i++) {
            int idx = i*128 + tid;
            int r = idx >> 4, c = idx & 15;
            long trow = (long)(b*TOK + k0 + r);
            *(float4*)&Ks[r][c*4] = *(const float4*)(qkv + trow*D3 + DMODEL   + h*HD + c*4);
            *(float4*)&Vs[r][c*4] = *(const float4*)(qkv + trow*D3 + 2*DMODEL + h*HD + c*4);
        }
        __syncthreads();

        // scores: thread computes keys k = kk*8 + lk (consecutive lanes -> consecutive k)
        float sreg[8];
        float tmax = -INFINITY;
        #pragma unroll
        for (int kk = 0; kk < 8; kk++) {
            int k = kk*8 + lk;
            float s = 0.f;
            #pragma unroll
            for (int d4 = 0; d4 < 16; d4++) {
                float4 qv = *(const float4*)&Qs[q][d4*4];
                float4 kv = *(const float4*)&Ks[k][d4*4];
                s += qv.x*kv.x + qv.y*kv.y + qv.z*kv.z + qv.w*kv.w;
            }
            s *= 0.125f;
            if (k0 + k > q0 + q) s = -INFINITY;    // causal mask
            sreg[kk] = s;
            tmax = fmaxf(tmax, s);
        }
        #pragma unroll
        for (int o = 1; o < 8; o <<= 1)
            tmax = fmaxf(tmax, __shfl_xor_sync(0xffffffffu, tmax, o));
        float mnew = fmaxf(mrow, tmax);            // finite: every tile has >=1 valid key
        float corr = __expf(0.f)*expf(mrow - mnew);
        float tsum = 0.f;
        #pragma unroll
        for (int kk = 0; kk < 8; kk++) {
            float p = expf(sreg[kk] - mnew);       // masked -> exp(-inf)=0
            Ps[q][kk*8 + lk] = p;
            tsum += p;
        }
        #pragma unroll
        for (int o = 1; o < 8; o <<= 1)
            tsum += __shfl_xor_sync(0xffffffffu, tsum, o);
        lrow = lrow * corr + tsum;
        mrow = mnew;
        #pragma unroll
        for (int d = 0; d < 8; d++) acc[d] *= corr;
        __syncwarp();                              // Ps[q] shared only within this warp

        // V accumulation: thread's 8 dims at d0
        const int d0 = lk*8;
        for (int k = 0; k < KT; k++) {
            float p = Ps[q][k];
            float4 v0 = *(const float4*)&Vs[k][d0];
            float4 v1 = *(const float4*)&Vs[k][d0+4];
            acc[0] += p*v0.x; acc[1] += p*v0.y; acc[2] += p*v0.z; acc[3] += p*v0.w;
            acc[4] += p*v1.x; acc[5] += p*v1.y; acc[6] += p*v1.z; acc[7] += p*v1.w;
        }
    }

    float inv = 1.f / lrow;
    long row = (long)(b*TOK) + q0 + q;
    __half* orow = out + row*DMODEL + h*HD + lk*8;
    #pragma unroll
    for (int d = 0; d < 8; d++)
        orow[d] = __float2half_rn(acc[d] * inv);
}

// ---------------- launcher ----------------
#define SYM(p, s) cudaGetSymbolAddress((void**)&p, s)

extern "C" void kernel_launch(void* const* d_in, const int* in_sizes, int n_in,
                              void* d_out, int out_size) {
    const int*   ids    = (const int*)  d_in[0];
    const float* wte    = (const float*)d_in[1];
    const float* wpe    = (const float*)d_in[2];
    const float* ln1_g  = (const float*)d_in[3];
    const float* ln1_b  = (const float*)d_in[4];
    const float* attn_w = (const float*)d_in[5];
    const float* attn_b = (const float*)d_in[6];
    const float* proj_w = (const float*)d_in[7];
    const float* proj_b = (const float*)d_in[8];
    const float* ln2_g  = (const float*)d_in[9];
    const float* ln2_b  = (const float*)d_in[10];
    const float* fc_w   = (const float*)d_in[11];
    const float* fc_b   = (const float*)d_in[12];
    const float* out_w  = (const float*)d_in[13];
    const float* out_b  = (const float*)d_in[14];
    const float* lnf_g  = (const float*)d_in[15];
    const float* lnf_b  = (const float*)d_in[16];
    float* logits = (float*)d_out;

    float *px, *pqkv;
    __half *ph, *pat, *pml, *wq, *wp, *wf, *wo, *wt;
    SYM(px, g_x); SYM(pqkv, g_qkv);
    SYM(ph, g_h); SYM(pat, g_attn); SYM(pml, g_mlp);
    SYM(wq, g_wq); SYM(wp, g_wp); SYM(wf, g_wf); SYM(wo, g_wo); SYM(wt, g_wt);

    const int SMEM = STAGES * STG_H * 2;   // 86,016 B
    cudaFuncSetAttribute(gemm_hmma<0>, cudaFuncAttributeMaxDynamicSharedMemorySize, SMEM);
    cudaFuncSetAttribute(gemm_hmma<1>, cudaFuncAttributeMaxDynamicSharedMemorySize, SMEM);
    cudaFuncSetAttribute(gemm_hmma<2>, cudaFuncAttributeMaxDynamicSharedMemorySize, SMEM);
    cudaFuncSetAttribute(gemm_hmma<3>, cudaFuncAttributeMaxDynamicSharedMemorySize, SMEM);

    prep_wt<<<dim3(D3/32, DMODEL/32, NLAYER), 256>>>(attn_w, wq, DMODEL, D3);
    prep_wt<<<dim3(DMODEL/32, DMODEL/32, NLAYER), 256>>>(proj_w, wp, DMODEL, DMODEL);
    prep_wt<<<dim3(D4/32, DMODEL/32, NLAYER), 256>>>(fc_w, wf, DMODEL, D4);
    prep_wt<<<dim3(DMODEL/32, D4/32, NLAYER), 256>>>(out_w, wo, D4, DMODEL);
    prep_wte<<<2048, 256>>>(wte, wt);

    embed_kernel<<<(ROWS*DMODEL + 255)/256, 256>>>(ids, wte, wpe, px);

    for (int l = 0; l < NLAYER; l++) {
        // --- attention block ---
        layernorm_kernel<<<ROWS, 256>>>(px, ln1_g + l*DMODEL, ln1_b + l*DMODEL, ph);
        gemm_hmma<0><<<dim3(ROWS/128, D3/128), 256, SMEM>>>(
            ph, wq + (long)l*D3*DMODEL, attn_b + l*D3, nullptr,
            pqkv, nullptr, D3, DMODEL);
        flash_attn_kernel<<<BATCH*NHEAD*(TOK/QT), 128>>>(pqkv, pat);
        gemm_hmma<1><<<dim3(ROWS/128, DMODEL/128), 256, SMEM>>>(
            pat, wp + (long)l*DMODEL*DMODEL, proj_b + l*DMODEL, px,
            px, nullptr, DMODEL, DMODEL);
        // --- mlp block ---
        layernorm_kernel<<<ROWS, 256>>>(px, ln2_g + l*DMODEL, ln2_b + l*DMODEL, ph);
        gemm_hmma<2><<<dim3(ROWS/128, D4/128), 256, SMEM>>>(
            ph, wf + (long)l*D4*DMODEL, fc_b + l*D4, nullptr,
            nullptr, pml, D4, DMODEL);
        gemm_hmma<1><<<dim3(ROWS/128, DMODEL/128), 256, SMEM>>>(
            pml, wo + (long)l*DMODEL*D4, out_b + l*DMODEL, px,
            px, nullptr, DMODEL, D4);
    }

    layernorm_kernel<<<ROWS, 256>>>(px, lnf_g, lnf_b, ph);
    gemm_hmma<3><<<dim3(ROWS/128, VPAD/128), 256, SMEM>>>(
        ph, wt, nullptr, nullptr, logits, nullptr, VOCAB, DMODEL);
}

// round 14
// speedup vs baseline: 7.1817x; 1.0328x over previous
#include <cuda_runtime.h>
#include <cuda_fp16.h>
#include <math.h>
#include <stdint.h>

#define BATCH 2
#define TOK   1024
#define ROWS  (BATCH*TOK)
#define DMODEL 768
#define NHEAD 12
#define HD    64
#define NLAYER 4
#define VOCAB 50257
#define VPAD  50432          // 394*128
#define D3    (3*DMODEL)
#define D4    (4*DMODEL)

// ---------------- scratch ----------------
__device__ __align__(128) float g_x  [ROWS*DMODEL];
__device__ __align__(128) float g_qkv[ROWS*D3];

__device__ __align__(128) __half g_h   [ROWS*DMODEL];
__device__ __align__(128) __half g_attn[ROWS*DMODEL];
__device__ __align__(128) __half g_mlp [ROWS*D4];

__device__ __align__(128) __half g_wq[NLAYER*D3*DMODEL];
__device__ __align__(128) __half g_wp[NLAYER*DMODEL*DMODEL];
__device__ __align__(128) __half g_wf[NLAYER*D4*DMODEL];
__device__ __align__(128) __half g_wo[NLAYER*DMODEL*D4];
__device__ __align__(128) __half g_wt[(long)VPAD*DMODEL];

// ---------------- helpers ----------------
__device__ __forceinline__ void cp16h(const __half* s, const __half* g) {
    uint32_t sa = (uint32_t)__cvta_generic_to_shared(s);
    asm volatile("cp.async.cg.shared.global [%0], [%1], 16;\n" :: "r"(sa), "l"(g));
}
__device__ __forceinline__ void cp_commit() { asm volatile("cp.async.commit_group;\n"); }
template<int N> __device__ __forceinline__ void cp_wait() {
    asm volatile("cp.async.wait_group %0;\n" :: "n"(N));
}
__device__ __forceinline__ void mma_fp16(float* c, const uint32_t* a, uint32_t b0, uint32_t b1) {
    asm volatile(
        "mma.sync.aligned.m16n8k16.row.col.f32.f16.f16.f32 "
        "{%0,%1,%2,%3}, {%4,%5,%6,%7}, {%8,%9}, {%0,%1,%2,%3};"
        : "+f"(c[0]), "+f"(c[1]), "+f"(c[2]), "+f"(c[3])
        : "r"(a[0]), "r"(a[1]), "r"(a[2]), "r"(a[3]), "r"(b0), "r"(b1));
}
__device__ __forceinline__ void ldsm4(uint32_t& r0, uint32_t& r1, uint32_t& r2, uint32_t& r3,
                                      uint32_t saddr) {
    asm volatile("ldmatrix.sync.aligned.m8n8.x4.shared.b16 {%0,%1,%2,%3}, [%4];"
                 : "=r"(r0), "=r"(r1), "=r"(r2), "=r"(r3) : "r"(saddr));
}

// ---------------- weight prep: w[K][N] fp32 -> fp16 [N][K] ----------------
__global__ void prep_wt(const float* __restrict__ w, __half* __restrict__ o, int K, int N) {
    __shared__ float t[32][33];
    int l = blockIdx.z;
    w += (long)l*K*N;  o += (long)l*N*K;
    int n0 = blockIdx.x*32, k0 = blockIdx.y*32;
    int tx = threadIdx.x & 31, ty = threadIdx.x >> 5;
    #pragma unroll
    for (int i = ty; i < 32; i += 8) t[i][tx] = w[(long)(k0+i)*N + n0 + tx];
    __syncthreads();
    #pragma unroll
    for (int i = ty; i < 32; i += 8)
        o[(long)(n0+i)*K + k0 + tx] = __float2half_rn(t[tx][i]);
}

__global__ void prep_wte(const float* __restrict__ w, __half* __restrict__ o) {
    long n = (long)VPAD*DMODEL;
    for (long i = blockIdx.x*(long)blockDim.x + threadIdx.x; i < n;
         i += (long)gridDim.x*blockDim.x) {
        long row = i / DMODEL;
        o[i] = __float2half_rn(row < VOCAB ? w[i] : 0.f);
    }
}

// ---------------- embedding ----------------
__global__ void embed_kernel(const int* __restrict__ ids, const float* __restrict__ wte,
                             const float* __restrict__ wpe, float* __restrict__ x) {
    int idx = blockIdx.x * blockDim.x + threadIdx.x;
    if (idx >= ROWS*DMODEL) return;
    int row = idx / DMODEL, d = idx - row*DMODEL, t = row % TOK;
    x[idx] = wte[(long)ids[row]*DMODEL + d] + wpe[t*DMODEL + d];
}

// ---------------- layernorm: warp per row -> fp16 ----------------
__global__ void __launch_bounds__(256)
layernorm_kernel(const float* __restrict__ x, const float* __restrict__ g,
                 const float* __restrict__ b, __half* __restrict__ out) {
    int warp = threadIdx.x >> 5, lane = threadIdx.x & 31;
    long r = (long)blockIdx.x*8 + warp;
    const float* xr = x + r*DMODEL;

    float4 v[6];
    float s = 0.f;
    #pragma unroll
    for (int i = 0; i < 6; i++) {
        v[i] = *(const float4*)(xr + (i*32 + lane)*4);
        s += v[i].x + v[i].y + v[i].z + v[i].w;
    }
    #pragma unroll
    for (int o = 16; o > 0; o >>= 1) s += __shfl_xor_sync(0xffffffffu, s, o);
    float mean = s * (1.f/DMODEL);

    float vs = 0.f;
    #pragma unroll
    for (int i = 0; i < 6; i++) {
        float dx = v[i].x-mean, dy = v[i].y-mean, dz = v[i].z-mean, dw = v[i].w-mean;
        vs += dx*dx + dy*dy + dz*dz + dw*dw;
    }
    #pragma unroll
    for (int o = 16; o > 0; o >>= 1) vs += __shfl_xor_sync(0xffffffffu, vs, o);
    float inv = rsqrtf(vs * (1.f/DMODEL) + 1e-5f);

    __half* orow = out + r*DMODEL;
    #pragma unroll
    for (int i = 0; i < 6; i++) {
        int c = (i*32 + lane)*4;
        float4 gg = *(const float4*)(g + c);
        float4 bb = *(const float4*)(b + c);
        __half2 h0 = __floats2half2_rn(gg.x*(v[i].x-mean)*inv + bb.x,
                                       gg.y*(v[i].y-mean)*inv + bb.y);
        __half2 h1 = __floats2half2_rn(gg.z*(v[i].z-mean)*inv + bb.z,
                                       gg.w*(v[i].w-mean)*inv + bb.w);
        *(__half2*)(orow + c)     = h0;
        *(__half2*)(orow + c + 2) = h1;
    }
}

// ---------------- fp16 HMMA GEMM: C[M,N] = A[M,K] @ B[N,K]^T ----------------
// Template BM in {64,128}; BN=128, BK=32, 256 threads, 8 warps 2(M)x4(N).
// EPI: 0 bias->C ; 1 bias+resid->C ; 2 bias+GELU->Ch fp16 ; 3 none->C, mask n<Nn.
#define ASTR   56
#define STAGES 3

template<int BM, int EPI>
__global__ void __launch_bounds__(256, 2)
gemm_hmma(const __half* __restrict__ A, const __half* __restrict__ B,
          const float* __restrict__ bias, const float* __restrict__ resid,
          float* __restrict__ C, __half* __restrict__ Ch,
          int Nn, int K) {
    constexpr int MTN    = BM/32;          // mt count per warp
    constexpr int AT_H   = BM*ASTR;        // A tile halves
    constexpr int BT_H   = 128*ASTR;       // B tile halves
    constexpr int STG_HH = AT_H + BT_H;

    extern __shared__ __half sh[];
    const uint32_t sbase = (uint32_t)__cvta_generic_to_shared(sh);
    const int tid = threadIdx.x, lane = tid & 31, warp = tid >> 5;
    const int wm = warp >> 2, wn = warp & 3;
    const long bm = (long)blockIdx.x * BM;
    const long bn = (long)blockIdx.y * 128;

    // per-lane ldmatrix row/col selectors
    const int arow = (lane & 7) + ((lane >> 3) & 1)*8;
    const int acol = (lane >> 4)*8;
    const int brow = (lane & 7) + ((lane >> 4) & 1)*8;
    const int bcol = ((lane >> 3) & 1)*8;

    float acc[MTN][4][4];
    #pragma unroll
    for (int i = 0; i < MTN; i++)
        #pragma unroll
        for (int j = 0; j < 4; j++)
            #pragma unroll
            for (int k = 0; k < 4; k++) acc[i][j][k] = 0.f;

    auto issue_load = [&](int s, int k0) {
        const __half* ab = A + bm*K + k0;
        const __half* bb = B + bn*K + k0;
        __half* sa  = sh + s*STG_HH;
        __half* sbm = sa + AT_H;
        #pragma unroll
        for (int i = 0; i < BM/64; i++) {
            int ch = i*256 + tid;
            int r = ch >> 2, c8 = (ch & 3) * 8;
            cp16h(sa + r*ASTR + c8, ab + (long)r*K + c8);
        }
        #pragma unroll
        for (int i = 0; i < 2; i++) {
            int ch = i*256 + tid;
            int r = ch >> 2, c8 = (ch & 3) * 8;
            cp16h(sbm + r*ASTR + c8, bb + (long)r*K + c8);
        }
        cp_commit();
    };

    auto compute = [&](int s) {
        uint32_t abase = sbase + (uint32_t)(s*STG_HH)*2;
        uint32_t bbase = abase + (uint32_t)AT_H*2;
        #pragma unroll
        for (int ks = 0; ks < 2; ks++) {
            const int k0 = ks*16;
            uint32_t af[MTN][4];
            #pragma unroll
            for (int mt = 0; mt < MTN; mt++)
                ldsm4(af[mt][0], af[mt][1], af[mt][2], af[mt][3],
                      abase + (uint32_t)((wm*(BM/2) + mt*16 + arow)*ASTR + k0 + acol)*2);
            uint32_t bf[4][2];
            #pragma unroll
            for (int p = 0; p < 2; p++)
                ldsm4(bf[2*p][0], bf[2*p][1], bf[2*p+1][0], bf[2*p+1][1],
                      bbase + (uint32_t)((wn*32 + p*16 + brow)*ASTR + k0 + bcol)*2);
            #pragma unroll
            for (int mt = 0; mt < MTN; mt++)
                #pragma unroll
                for (int nt = 0; nt < 4; nt++)
                    mma_fp16(acc[mt][nt], af[mt], bf[nt][0], bf[nt][1]);
        }
    };

    const int NIT = K / 32;
    #pragma unroll
    for (int s = 0; s < STAGES-1; s++) issue_load(s, s*32);

    for (int it = 0; it < NIT; ++it) {
        cp_wait<STAGES-2>();
        __syncthreads();
        int nxt = it + STAGES - 1;
        if (nxt < NIT) issue_load(nxt % STAGES, nxt*32);
        else cp_commit();
        compute(it % STAGES);
    }

    // epilogue
    #pragma unroll
    for (int mt = 0; mt < MTN; mt++) {
        #pragma unroll
        for (int nt = 0; nt < 4; nt++) {
            long row0 = bm + wm*(BM/2) + mt*16 + (lane >> 2);
            long col0 = bn + wn*32 + nt*8 + (lane & 3)*2;
            #pragma unroll
            for (int h = 0; h < 2; h++) {
                long m = row0 + h*8;
                #pragma unroll
                for (int j = 0; j < 2; j++) {
                    long n = col0 + j;
                    float v = acc[mt][nt][h*2 + j];
                    if (EPI != 3) v += bias[n];
                    if (EPI == 1) v += resid[m*Nn + n];
                    if (EPI == 2) {
                        float gv = 0.5f * v * (1.f + erff(v * 0.70710678118654752f));
                        Ch[m*Nn + n] = __float2half_rn(gv);
                    } else if (EPI == 3) {
                        if (n < Nn) C[m*Nn + n] = v;
                    } else {
                        C[m*Nn + n] = v;
                    }
                }
            }
        }
    }
}

// ---------------- flash attention: block = (b, h, 16 q-rows) ----------------
#define QT 16
#define KT 64

__global__ void __launch_bounds__(128)
flash_attn_kernel(const float* __restrict__ qkv, __half* __restrict__ out) {
    __shared__ float Qs[QT][68];
    __shared__ float Ks[KT][68];
    __shared__ float Vs[KT][68];
    __shared__ float Ps[QT][68];

    const int bid = blockIdx.x;
    const int qt = bid & 63;
    const int h  = (bid >> 6) % NHEAD;
    const int b  = bid / (64*NHEAD);
    const int tid = threadIdx.x;
    const int q0 = qt * QT;

    #pragma unroll
    for (int i = 0; i < 2; i++) {
        int idx = i*128 + tid;
        int r = idx >> 4, c = idx & 15;
        *(float4*)&Qs[r][c*4] =
            *(const float4*)(qkv + ((long)(b*TOK + q0 + r))*D3 + h*HD + c*4);
    }

    const int q  = tid >> 3;
    const int lk = tid & 7;
    float acc[8];
    #pragma unroll
    for (int d = 0; d < 8; d++) acc[d] = 0.f;
    float mrow = -INFINITY, lrow = 0.f;

    const int kend = q0 + QT;
    for (int k0 = 0; k0 < kend; k0 += KT) {
        __syncthreads();
        #pragma unroll
        for (int i = 0; i < 8; i++) {
            int idx = i*128 + tid;
            int r = idx >> 4, c = idx & 15;
            long trow = (long)(b*TOK + k0 + r);
            *(float4*)&Ks[r][c*4] = *(const float4*)(qkv + trow*D3 + DMODEL   + h*HD + c*4);
            *(float4*)&Vs[r][c*4] = *(const float4*)(qkv + trow*D3 + 2*DMODEL + h*HD + c*4);
        }
        __syncthreads();

        float sreg[8];
        float tmax = -INFINITY;
        #pragma unroll
        for (int kk = 0; kk < 8; kk++) {
            int k = kk*8 + lk;
            float s = 0.f;
            #pragma unroll
            for (int d4 = 0; d4 < 16; d4++) {
                float4 qv = *(const float4*)&Qs[q][d4*4];
                float4 kv = *(const float4*)&Ks[k][d4*4];
                s += qv.x*kv.x + qv.y*kv.y + qv.z*kv.z + qv.w*kv.w;
            }
            s *= 0.125f;
            if (k0 + k > q0 + q) s = -INFINITY;
            sreg[kk] = s;
            tmax = fmaxf(tmax, s);
        }
        #pragma unroll
        for (int o = 1; o < 8; o <<= 1)
            tmax = fmaxf(tmax, __shfl_xor_sync(0xffffffffu, tmax, o));
        float mnew = fmaxf(mrow, tmax);
        float corr = expf(mrow - mnew);
        float tsum = 0.f;
        #pragma unroll
        for (int kk = 0; kk < 8; kk++) {
            float p = expf(sreg[kk] - mnew);
            Ps[q][kk*8 + lk] = p;
            tsum += p;
        }
        #pragma unroll
        for (int o = 1; o < 8; o <<= 1)
            tsum += __shfl_xor_sync(0xffffffffu, tsum, o);
        lrow = lrow * corr + tsum;
        mrow = mnew;
        #pragma unroll
        for (int d = 0; d < 8; d++) acc[d] *= corr;
        __syncwarp();

        const int d0 = lk*8;
        for (int k = 0; k < KT; k++) {
            float p = Ps[q][k];
            float4 v0 = *(const float4*)&Vs[k][d0];
            float4 v1 = *(const float4*)&Vs[k][d0+4];
            acc[0] += p*v0.x; acc[1] += p*v0.y; acc[2] += p*v0.z; acc[3] += p*v0.w;
            acc[4] += p*v1.x; acc[5] += p*v1.y; acc[6] += p*v1.z; acc[7] += p*v1.w;
        }
    }

    float inv = 1.f / lrow;
    long row = (long)(b*TOK) + q0 + q;
    __half* orow = out + row*DMODEL + h*HD + lk*8;
    #pragma unroll
    for (int d = 0; d < 8; d++)
        orow[d] = __float2half_rn(acc[d] * inv);
}

// ---------------- launcher ----------------
#define SYM(p, s) cudaGetSymbolAddress((void**)&p, s)

extern "C" void kernel_launch(void* const* d_in, const int* in_sizes, int n_in,
                              void* d_out, int out_size) {
    const int*   ids    = (const int*)  d_in[0];
    const float* wte    = (const float*)d_in[1];
    const float* wpe    = (const float*)d_in[2];
    const float* ln1_g  = (const float*)d_in[3];
    const float* ln1_b  = (const float*)d_in[4];
    const float* attn_w = (const float*)d_in[5];
    const float* attn_b = (const float*)d_in[6];
    const float* proj_w = (const float*)d_in[7];
    const float* proj_b = (const float*)d_in[8];
    const float* ln2_g  = (const float*)d_in[9];
    const float* ln2_b  = (const float*)d_in[10];
    const float* fc_w   = (const float*)d_in[11];
    const float* fc_b   = (const float*)d_in[12];
    const float* out_w  = (const float*)d_in[13];
    const float* out_b  = (const float*)d_in[14];
    const float* lnf_g  = (const float*)d_in[15];
    const float* lnf_b  = (const float*)d_in[16];
    float* logits = (float*)d_out;

    float *px, *pqkv;
    __half *ph, *pat, *pml, *wq, *wp, *wf, *wo, *wt;
    SYM(px, g_x); SYM(pqkv, g_qkv);
    SYM(ph, g_h); SYM(pat, g_attn); SYM(pml, g_mlp);
    SYM(wq, g_wq); SYM(wp, g_wp); SYM(wf, g_wf); SYM(wo, g_wo); SYM(wt, g_wt);

    const int SMEM128 = STAGES * (128+128) * ASTR * 2;   // 86,016 B
    const int SMEM64  = STAGES * (64+128)  * ASTR * 2;   // 64,512 B
    cudaFuncSetAttribute(gemm_hmma<128,0>, cudaFuncAttributeMaxDynamicSharedMemorySize, SMEM128);
    cudaFuncSetAttribute(gemm_hmma<128,3>, cudaFuncAttributeMaxDynamicSharedMemorySize, SMEM128);
    cudaFuncSetAttribute(gemm_hmma<64,1>,  cudaFuncAttributeMaxDynamicSharedMemorySize, SMEM64);
    cudaFuncSetAttribute(gemm_hmma<64,2>,  cudaFuncAttributeMaxDynamicSharedMemorySize, SMEM64);

    prep_wt<<<dim3(D3/32, DMODEL/32, NLAYER), 256>>>(attn_w, wq, DMODEL, D3);
    prep_wt<<<dim3(DMODEL/32, DMODEL/32, NLAYER), 256>>>(proj_w, wp, DMODEL, DMODEL);
    prep_wt<<<dim3(D4/32, DMODEL/32, NLAYER), 256>>>(fc_w, wf, DMODEL, D4);
    prep_wt<<<dim3(DMODEL/32, D4/32, NLAYER), 256>>>(out_w, wo, D4, DMODEL);
    prep_wte<<<2048, 256>>>(wte, wt);

    embed_kernel<<<(ROWS*DMODEL + 255)/256, 256>>>(ids, wte, wpe, px);

    for (int l = 0; l < NLAYER; l++) {
        // --- attention block ---
        layernorm_kernel<<<ROWS/8, 256>>>(px, ln1_g + l*DMODEL, ln1_b + l*DMODEL, ph);
        gemm_hmma<128,0><<<dim3(ROWS/128, D3/128), 256, SMEM128>>>(
            ph, wq + (long)l*D3*DMODEL, attn_b + l*D3, nullptr,
            pqkv, nullptr, D3, DMODEL);
        flash_attn_kernel<<<BATCH*NHEAD*(TOK/QT), 128>>>(pqkv, pat);
        gemm_hmma<64,1><<<dim3(ROWS/64, DMODEL/128), 256, SMEM64>>>(
            pat, wp + (long)l*DMODEL*DMODEL, proj_b + l*DMODEL, px,
            px, nullptr, DMODEL, DMODEL);
        // --- mlp block ---
        layernorm_kernel<<<ROWS/8, 256>>>(px, ln2_g + l*DMODEL, ln2_b + l*DMODEL, ph);
        gemm_hmma<64,2><<<dim3(ROWS/64, D4/128), 256, SMEM64>>>(
            ph, wf + (long)l*D4*DMODEL, fc_b + l*D4, nullptr,
            nullptr, pml, D4, DMODEL);
        gemm_hmma<64,1><<<dim3(ROWS/64, DMODEL/128), 256, SMEM64>>>(
            pml, wo + (long)l*DMODEL*D4, out_b + l*DMODEL, px,
            px, nullptr, DMODEL, D4);
    }

    layernorm_kernel<<<ROWS/8, 256>>>(px, lnf_g, lnf_b, ph);
    gemm_hmma<128,3><<<dim3(ROWS/128, VPAD/128), 256, SMEM128>>>(
        ph, wt, nullptr, nullptr, logits, nullptr, VOCAB, DMODEL);
}